// round 14
// baseline (speedup 1.0000x reference)
#include <cuda_runtime.h>
#include <math.h>

#define NN    50000
#define FIN   512
#define HEADS 4
#define HID   64
#define NCLS  40
#define EE    800000
#define ETOT  (EE + NN)      // 850000 (with self loops)
#define D1    (HEADS * HID)  // 256

// ---------------- scratch (device globals; no allocation allowed) ----------
static __device__ float g_h  [(size_t)NN * D1];      // GEMM output h
static __device__ float g_buf[(size_t)NN * D1];      // aggregated output / next input
static __device__ float g_as [NN * HEADS];
static __device__ float g_ad [NN * HEADS];
static __device__ int   g_deg[NN];
static __device__ int   g_off[NN + 1];
static __device__ int   g_cur[NN];
static __device__ int   g_srcs[ETOT];                // src node ids grouped by dst
// pre-split weights (hi,lo tf32 pairs), zero-padded row stride
static __device__ uint2 g_w1s[FIN * D1];             // 512x256, stride 256
static __device__ uint2 g_w2s[D1 * D1];              // 256x256, stride 256
static __device__ uint2 g_w3s[D1 * 128];             // 256x128 (N=40 zero-padded)

// ---------------- side stream for CSR overlap --------------------------------
static cudaStream_t g_s2;
static cudaEvent_t  g_evFork, g_evJoin;
namespace {
struct SideStreamInit {
    SideStreamInit() {
        cudaStreamCreateWithFlags(&g_s2, cudaStreamNonBlocking);
        cudaEventCreateWithFlags(&g_evFork, cudaEventDisableTiming);
        cudaEventCreateWithFlags(&g_evJoin, cudaEventDisableTiming);
    }
};
SideStreamInit g_side_stream_init;
}

// ---------------- tf32 helpers ---------------------------------------------
__device__ __forceinline__ unsigned f2tf(float f) {
    unsigned u;
    asm("cvt.rna.tf32.f32 %0, %1;" : "=r"(u) : "f"(f));
    return u;
}
__device__ __forceinline__ void tf_split(float f, unsigned& hi, unsigned& lo) {
    hi = f2tf(f);
    float r = f - __uint_as_float(hi);
    lo = f2tf(r);
}
__device__ __forceinline__ uint2 split2(float f) {
    unsigned hi = f2tf(f);
    float r = f - __uint_as_float(hi);
    return make_uint2(hi, f2tf(r));
}
__device__ __forceinline__ void mma_tf32(float c[4],
                                         unsigned a0, unsigned a1, unsigned a2, unsigned a3,
                                         unsigned b0, unsigned b1) {
    asm volatile(
        "mma.sync.aligned.m16n8k8.row.col.f32.tf32.tf32.f32 "
        "{%0,%1,%2,%3}, {%4,%5,%6,%7}, {%8,%9}, {%0,%1,%2,%3};"
        : "+f"(c[0]), "+f"(c[1]), "+f"(c[2]), "+f"(c[3])
        : "r"(a0), "r"(a1), "r"(a2), "r"(a3), "r"(b0), "r"(b1));
}

__device__ __forceinline__ void cp16(unsigned dst, const void* src) {
    asm volatile("cp.async.cg.shared.global [%0], [%1], 16;"
                 :: "r"(dst), "l"(src));
}

// ---------------- no-op (aligns ncu's sampled launch onto the GEMM) ---------
__global__ void k_noop() {}

// ---------------- pre-split all three W matrices -----------------------------
__global__ void w_split_all(const float* __restrict__ W1,
                            const float* __restrict__ W2,
                            const float* __restrict__ W3) {
    int idx = blockIdx.x * blockDim.x + threadIdx.x;
    const int n1 = FIN * D1;          // W1: 512x256
    const int n2 = D1 * D1;           // W2: 256x256
    const int n3 = D1 * 128;          // W3 padded: 256x128
    if (idx < n1) {
        g_w1s[idx] = split2(W1[idx]);
    } else if (idx < n1 + n2) {
        int i = idx - n1;
        g_w2s[i] = split2(W2[i]);
    } else if (idx < n1 + n2 + n3) {
        int i = idx - n1 - n2;
        int k = i >> 7, n = i & 127;
        g_w3s[i] = split2(n < NCLS ? W3[k * NCLS + n] : 0.f);
    }
}

// ---------------- GEMM: C[M,N] = A[M,K] @ Wsplit, 3xTF32 tensor cores ------
// 3-stage cp.async pipeline. A raw (split in-loop); B pre-split uint2 loaded
// straight to MMA operands (no B splits in the hot loop).
#define BK  16
#define SAK 20    // A smem k-stride (floats; 16 + 4 pad)
#define SB2 132   // B smem n-stride (uint2)
#define STAGES 3
#define A_STG (128 * SAK)              // floats per A stage
#define B_STG (BK * SB2)               // uint2 per B stage
#define GEMM_SMEM_BYTES ((A_STG * 4 + B_STG * 8) * STAGES)   // 81408

__global__ void __launch_bounds__(256) gemm_tf32(const float* __restrict__ A,
                                                 const uint2* __restrict__ Ws,
                                                 float* __restrict__ C,
                                                 int M, int N, int K, int NP) {
    extern __shared__ float sm[];
    float* As  = sm;                              // [STAGES][128][SAK]
    uint2* Bs2 = (uint2*)(sm + STAGES * A_STG);   // [STAGES][BK][SB2]

    int tid  = threadIdx.x;
    int lane = tid & 31;
    int wid  = tid >> 5;
    int warpM = wid & 1;
    int warpN = wid >> 1;
    int g = lane >> 2, t = lane & 3;

    int bm = blockIdx.x * 128;
    int bn = blockIdx.y * 128;

    float acc[4][4][4];
#pragma unroll
    for (int i = 0; i < 4; i++)
#pragma unroll
        for (int j = 0; j < 4; j++)
#pragma unroll
            for (int q = 0; q < 4; q++) acc[i][j][q] = 0.f;

    int ar = tid >> 1;
    int ak = (tid & 1) * 8;
    int bkr = tid >> 4;            // 0..15
    int bc  = (tid & 15) * 8;      // 0..120 (uint2 units)
    int arow = bm + ar; if (arow >= M) arow = M - 1;
    const float* aptr = A + (size_t)arow * K + ak;
    const uint2* bptr = Ws + (size_t)bkr * NP + bn + bc;

    unsigned dA = (unsigned)__cvta_generic_to_shared(As) + (ar * SAK + ak) * 4;
    unsigned dB = (unsigned)__cvta_generic_to_shared(Bs2) + (bkr * SB2 + bc) * 8;
    const unsigned stA = A_STG * 4;
    const unsigned stB = B_STG * 8;

    int T = K / BK;
    // prologue: tiles 0,1 -> stages 0,1
    cp16(dA,      aptr);
    cp16(dA + 16, aptr + 4);
    cp16(dB,      bptr);
    cp16(dB + 16, bptr + 2);
    cp16(dB + 32, bptr + 4);
    cp16(dB + 48, bptr + 6);
    asm volatile("cp.async.commit_group;");
    if (T > 1) {
        const float* ap = aptr + BK;
        const uint2* bp = bptr + (size_t)BK * NP;
        cp16(dA + stA,      ap);
        cp16(dA + stA + 16, ap + 4);
        cp16(dB + stB,      bp);
        cp16(dB + stB + 16, bp + 2);
        cp16(dB + stB + 32, bp + 4);
        cp16(dB + stB + 48, bp + 6);
    }
    asm volatile("cp.async.commit_group;");

    int rowb = warpM * 64 + g;
    int colb = warpN * 32 + g;

    for (int tt = 0; tt < T; tt++) {
        int cur = tt % STAGES;
        if (tt + 2 < T) {
            int nxt = (tt + 2) % STAGES;
            const float* ap = aptr + (tt + 2) * BK;
            const uint2* bp = bptr + (size_t)(tt + 2) * BK * NP;
            cp16(dA + nxt * stA,      ap);
            cp16(dA + nxt * stA + 16, ap + 4);
            cp16(dB + nxt * stB,      bp);
            cp16(dB + nxt * stB + 16, bp + 2);
            cp16(dB + nxt * stB + 32, bp + 4);
            cp16(dB + nxt * stB + 48, bp + 6);
        }
        asm volatile("cp.async.commit_group;");
        asm volatile("cp.async.wait_group 2;");
        __syncthreads();

        const float* Af = As  + cur * A_STG;
        const uint2* Bf = Bs2 + cur * B_STG;
#pragma unroll
        for (int kk = 0; kk < BK; kk += 8) {
            unsigned aHi[4][4], aLo[4][4];
            uint2 bF[4][2];
#pragma unroll
            for (int mt = 0; mt < 4; mt++) {
                int r = rowb + mt * 16;
                tf_split(Af[(r    ) * SAK + kk + t    ], aHi[mt][0], aLo[mt][0]);
                tf_split(Af[(r + 8) * SAK + kk + t    ], aHi[mt][1], aLo[mt][1]);
                tf_split(Af[(r    ) * SAK + kk + t + 4], aHi[mt][2], aLo[mt][2]);
                tf_split(Af[(r + 8) * SAK + kk + t + 4], aHi[mt][3], aLo[mt][3]);
            }
#pragma unroll
            for (int nt = 0; nt < 4; nt++) {
                int c = colb + nt * 8;
                bF[nt][0] = Bf[(kk + t    ) * SB2 + c];
                bF[nt][1] = Bf[(kk + t + 4) * SB2 + c];
            }
#pragma unroll
            for (int mt = 0; mt < 4; mt++)
#pragma unroll
                for (int nt = 0; nt < 4; nt++) {
                    mma_tf32(acc[mt][nt], aHi[mt][0], aHi[mt][1], aHi[mt][2], aHi[mt][3],
                             bF[nt][0].y, bF[nt][1].y);
                    mma_tf32(acc[mt][nt], aLo[mt][0], aLo[mt][1], aLo[mt][2], aLo[mt][3],
                             bF[nt][0].x, bF[nt][1].x);
                    mma_tf32(acc[mt][nt], aHi[mt][0], aHi[mt][1], aHi[mt][2], aHi[mt][3],
                             bF[nt][0].x, bF[nt][1].x);
                }
        }
        __syncthreads();
    }

#pragma unroll
    for (int mt = 0; mt < 4; mt++) {
        int row0 = bm + warpM * 64 + mt * 16 + g;
#pragma unroll
        for (int nt = 0; nt < 4; nt++) {
            int col = bn + warpN * 32 + nt * 8 + 2 * t;
            if (col < N) {
                if (row0 < M)
                    *(float2*)&C[(size_t)row0 * N + col] =
                        make_float2(acc[mt][nt][0], acc[mt][nt][1]);
                if (row0 + 8 < M)
                    *(float2*)&C[(size_t)(row0 + 8) * N + col] =
                        make_float2(acc[mt][nt][2], acc[mt][nt][3]);
            }
        }
    }
}

// ---------------- CSR build --------------------------------------------------
__global__ void k_zero_deg() {
    int i = blockIdx.x * blockDim.x + threadIdx.x;
    if (i < NN) g_deg[i] = 0;
}

__global__ void k_count(const int* __restrict__ ei) {
    int e = blockIdx.x * blockDim.x + threadIdx.x;
    if (e >= ETOT) return;
    int d = e < EE ? ei[EE + e] : e - EE;
    atomicAdd(&g_deg[d], 1);
}

__global__ __launch_bounds__(1024) void k_scan() {
    __shared__ int part[1024];
    const int SEG = (NN + 1023) / 1024;
    int t = threadIdx.x;
    int lo = t * SEG, hi = min(NN, lo + SEG);
    int s = 0;
    for (int i = lo; i < hi; i++) s += g_deg[i];
    part[t] = s;
    __syncthreads();
    for (int off = 1; off < 1024; off <<= 1) {
        int v = 0;
        if (t >= off) v = part[t - off];
        __syncthreads();
        if (t >= off) part[t] += v;
        __syncthreads();
    }
    int run = t ? part[t - 1] : 0;
    for (int i = lo; i < hi; i++) {
        g_off[i] = run;
        g_cur[i] = run;
        run += g_deg[i];
    }
    if (t == 0) g_off[NN] = part[1023];
}

__global__ void k_scatter(const int* __restrict__ ei) {
    int e = blockIdx.x * blockDim.x + threadIdx.x;
    if (e >= ETOT) return;
    int s, d;
    if (e < EE) { s = ei[e]; d = ei[EE + e]; }
    else        { s = d = e - EE; }
    int pos = atomicAdd(&g_cur[d], 1);
    g_srcs[pos] = s;
}

// ---------------- per-node: a_s, a_d -----------------------------------------
__global__ void node_prep(const float* __restrict__ h,
                          const float* __restrict__ atts,
                          const float* __restrict__ attd,
                          int H, int C) {
    int warp = (blockIdx.x * blockDim.x + threadIdx.x) >> 5;
    int lane = threadIdx.x & 31;
    if (warp >= NN) return;
    int HC = H * C;
    const float* hr = h + (size_t)warp * HC;
    for (int hd = 0; hd < H; hd++) {
        float s = 0.f, d = 0.f;
        for (int c = lane; c < C; c += 32) {
            float v = hr[hd * C + c];
            s += v * atts[hd * C + c];
            d += v * attd[hd * C + c];
        }
#pragma unroll
        for (int o = 16; o; o >>= 1) {
            s += __shfl_down_sync(0xFFFFFFFFu, s, o);
            d += __shfl_down_sync(0xFFFFFFFFu, d, o);
        }
        if (lane == 0) {
            g_as[warp * H + hd] = s;
            g_ad[warp * H + hd] = d;
        }
    }
}

// ---------------- fused softmax + aggregation (H=4, 256 ch) -----------------
__global__ __launch_bounds__(256) void aggr_fused4(const float* __restrict__ h,
                                                   const float* __restrict__ bias,
                                                   float* __restrict__ obuf,
                                                   int apply_elu) {
    __shared__ float4 earr[8][32];
    __shared__ int    sarr[8][32];
    int wrp  = threadIdx.x >> 5;
    int node = (blockIdx.x * blockDim.x + threadIdx.x) >> 5;
    int lane = threadIdx.x & 31;
    if (node >= NN) return;
    int beg = g_off[node];
    int deg = g_off[node + 1] - beg;

    float4 adv = *(const float4*)&g_ad[node * 4];

    // ---- pass 1: per-head max; cache first-block logits + srcs ----
    float c0 = 0.f, c1 = 0.f, c2 = 0.f, c3 = 0.f;
    int   sv = 0;
    float mx0 = -1e30f, mx1 = -1e30f, mx2 = -1e30f, mx3 = -1e30f;
    if (lane < deg) {
        sv = g_srcs[beg + lane];
        float4 av = *(const float4*)&g_as[sv * 4];
        c0 = av.x + adv.x; c1 = av.y + adv.y;
        c2 = av.z + adv.z; c3 = av.w + adv.w;
        c0 = c0 > 0.f ? c0 : 0.2f * c0;
        c1 = c1 > 0.f ? c1 : 0.2f * c1;
        c2 = c2 > 0.f ? c2 : 0.2f * c2;
        c3 = c3 > 0.f ? c3 : 0.2f * c3;
        mx0 = c0; mx1 = c1; mx2 = c2; mx3 = c3;
    }
    for (int base = 32; base < deg; base += 32) {
        int i = base + lane;
        if (i < deg) {
            int s = g_srcs[beg + i];
            float4 av = *(const float4*)&g_as[s * 4];
            float v0 = av.x + adv.x, v1 = av.y + adv.y;
            float v2 = av.z + adv.z, v3 = av.w + adv.w;
            v0 = v0 > 0.f ? v0 : 0.2f * v0;
            v1 = v1 > 0.f ? v1 : 0.2f * v1;
            v2 = v2 > 0.f ? v2 : 0.2f * v2;
            v3 = v3 > 0.f ? v3 : 0.2f * v3;
            mx0 = fmaxf(mx0, v0); mx1 = fmaxf(mx1, v1);
            mx2 = fmaxf(mx2, v2); mx3 = fmaxf(mx3, v3);
        }
    }
#pragma unroll
    for (int o = 16; o; o >>= 1) {
        mx0 = fmaxf(mx0, __shfl_xor_sync(0xFFFFFFFFu, mx0, o));
        mx1 = fmaxf(mx1, __shfl_xor_sync(0xFFFFFFFFu, mx1, o));
        mx2 = fmaxf(mx2, __shfl_xor_sync(0xFFFFFFFFu, mx2, o));
        mx3 = fmaxf(mx3, __shfl_xor_sync(0xFFFFFFFFu, mx3, o));
    }

    // ---- pass 2: exp -> smem, aggregate (unroll 4) + denominator ----
    int c8 = lane * 8, hd = lane >> 3;
    float4 a0 = make_float4(0.f, 0.f, 0.f, 0.f);
    float4 a1 = make_float4(0.f, 0.f, 0.f, 0.f);
    float ssum = 0.f;

    for (int base = 0; base < deg; base += 32) {
        int len = min(32, deg - base);
        if (lane < len) {
            float v0, v1, v2, v3; int s;
            if (base == 0) { v0 = c0; v1 = c1; v2 = c2; v3 = c3; s = sv; }
            else {
                s = g_srcs[beg + base + lane];
                float4 av = *(const float4*)&g_as[s * 4];
                v0 = av.x + adv.x; v1 = av.y + adv.y;
                v2 = av.z + adv.z; v3 = av.w + adv.w;
                v0 = v0 > 0.f ? v0 : 0.2f * v0;
                v1 = v1 > 0.f ? v1 : 0.2f * v1;
                v2 = v2 > 0.f ? v2 : 0.2f * v2;
                v3 = v3 > 0.f ? v3 : 0.2f * v3;
            }
            earr[wrp][lane] = make_float4(__expf(v0 - mx0), __expf(v1 - mx1),
                                          __expf(v2 - mx2), __expf(v3 - mx3));
            sarr[wrp][lane] = s;
        }
        __syncwarp();
        int i = 0;
        for (; i + 4 <= len; i += 4) {
            float4 cfA = earr[wrp][i];
            float4 cfB = earr[wrp][i + 1];
            float4 cfC = earr[wrp][i + 2];
            float4 cfD = earr[wrp][i + 3];
            int sA = sarr[wrp][i];
            int sB = sarr[wrp][i + 1];
            int sC = sarr[wrp][i + 2];
            int sD = sarr[wrp][i + 3];
            float kA = hd == 0 ? cfA.x : hd == 1 ? cfA.y : hd == 2 ? cfA.z : cfA.w;
            float kB = hd == 0 ? cfB.x : hd == 1 ? cfB.y : hd == 2 ? cfB.z : cfB.w;
            float kC = hd == 0 ? cfC.x : hd == 1 ? cfC.y : hd == 2 ? cfC.z : cfC.w;
            float kD = hd == 0 ? cfD.x : hd == 1 ? cfD.y : hd == 2 ? cfD.z : cfD.w;
            const float4* hA = (const float4*)(h + (size_t)sA * 256 + c8);
            const float4* hB = (const float4*)(h + (size_t)sB * 256 + c8);
            const float4* hC = (const float4*)(h + (size_t)sC * 256 + c8);
            const float4* hD = (const float4*)(h + (size_t)sD * 256 + c8);
            float4 uA0 = hA[0], uA1 = hA[1];
            float4 uB0 = hB[0], uB1 = hB[1];
            float4 uC0 = hC[0], uC1 = hC[1];
            float4 uD0 = hD[0], uD1 = hD[1];
            a0.x += kA * uA0.x; a0.y += kA * uA0.y; a0.z += kA * uA0.z; a0.w += kA * uA0.w;
            a1.x += kA * uA1.x; a1.y += kA * uA1.y; a1.z += kA * uA1.z; a1.w += kA * uA1.w;
            a0.x += kB * uB0.x; a0.y += kB * uB0.y; a0.z += kB * uB0.z; a0.w += kB * uB0.w;
            a1.x += kB * uB1.x; a1.y += kB * uB1.y; a1.z += kB * uB1.z; a1.w += kB * uB1.w;
            a0.x += kC * uC0.x; a0.y += kC * uC0.y; a0.z += kC * uC0.z; a0.w += kC * uC0.w;
            a1.x += kC * uC1.x; a1.y += kC * uC1.y; a1.z += kC * uC1.z; a1.w += kC * uC1.w;
            a0.x += kD * uD0.x; a0.y += kD * uD0.y; a0.z += kD * uD0.z; a0.w += kD * uD0.w;
            a1.x += kD * uD1.x; a1.y += kD * uD1.y; a1.z += kD * uD1.z; a1.w += kD * uD1.w;
            ssum += kA + kB + kC + kD;
        }
        for (; i < len; i++) {
            float4 cfA = earr[wrp][i];
            int sA = sarr[wrp][i];
            float kA = hd == 0 ? cfA.x : hd == 1 ? cfA.y : hd == 2 ? cfA.z : cfA.w;
            const float4* hA = (const float4*)(h + (size_t)sA * 256 + c8);
            float4 uA0 = hA[0], uA1 = hA[1];
            a0.x += kA * uA0.x; a0.y += kA * uA0.y; a0.z += kA * uA0.z; a0.w += kA * uA0.w;
            a1.x += kA * uA1.x; a1.y += kA * uA1.y; a1.z += kA * uA1.z; a1.w += kA * uA1.w;
            ssum += kA;
        }
        __syncwarp();   // protect smem before next block overwrites
    }

    float r = 1.f / ssum;
    float4 b0 = *(const float4*)&bias[c8];
    float4 b1 = *(const float4*)&bias[c8 + 4];
    a0.x = a0.x * r + b0.x; a0.y = a0.y * r + b0.y;
    a0.z = a0.z * r + b0.z; a0.w = a0.w * r + b0.w;
    a1.x = a1.x * r + b1.x; a1.y = a1.y * r + b1.y;
    a1.z = a1.z * r + b1.z; a1.w = a1.w * r + b1.w;
    if (apply_elu) {
        a0.x = a0.x > 0.f ? a0.x : expm1f(a0.x);
        a0.y = a0.y > 0.f ? a0.y : expm1f(a0.y);
        a0.z = a0.z > 0.f ? a0.z : expm1f(a0.z);
        a0.w = a0.w > 0.f ? a0.w : expm1f(a0.w);
        a1.x = a1.x > 0.f ? a1.x : expm1f(a1.x);
        a1.y = a1.y > 0.f ? a1.y : expm1f(a1.y);
        a1.z = a1.z > 0.f ? a1.z : expm1f(a1.z);
        a1.w = a1.w > 0.f ? a1.w : expm1f(a1.w);
    }
    float4* op = (float4*)(obuf + (size_t)node * 256 + c8);
    op[0] = a0;
    op[1] = a1;
}

// ---------------- fused softmax + aggregation (H=1, 40 ch) -------------------
__global__ __launch_bounds__(256) void aggr_fused40(const float* __restrict__ h,
                                                    const float* __restrict__ bias,
                                                    float* __restrict__ out) {
    __shared__ float earr[8][32];
    __shared__ int   sarr[8][32];
    int wrp  = threadIdx.x >> 5;
    int node = (blockIdx.x * blockDim.x + threadIdx.x) >> 5;
    int lane = threadIdx.x & 31;
    if (node >= NN) return;
    int beg = g_off[node];
    int deg = g_off[node + 1] - beg;

    float adv = g_ad[node];

    // pass 1: max; cache first block
    float vc = 0.f;
    int   sv = 0;
    float mx = -1e30f;
    if (lane < deg) {
        sv = g_srcs[beg + lane];
        float v = g_as[sv] + adv;
        vc = v > 0.f ? v : 0.2f * v;
        mx = vc;
    }
    for (int base = 32; base < deg; base += 32) {
        int i = base + lane;
        if (i < deg) {
            int s = g_srcs[beg + i];
            float v = g_as[s] + adv;
            v = v > 0.f ? v : 0.2f * v;
            mx = fmaxf(mx, v);
        }
    }
#pragma unroll
    for (int o = 16; o; o >>= 1) mx = fmaxf(mx, __shfl_xor_sync(0xFFFFFFFFu, mx, o));

    // pass 2: exp -> smem, aggregate (unroll 4) + denominator
    float4 acc = make_float4(0.f, 0.f, 0.f, 0.f);
    int c4 = lane * 4;
    bool act = lane < 10;
    float ssum = 0.f;

    for (int base = 0; base < deg; base += 32) {
        int len = min(32, deg - base);
        if (lane < len) {
            float v; int s;
            if (base == 0) { v = vc; s = sv; }
            else {
                s = g_srcs[beg + base + lane];
                float w = g_as[s] + adv;
                v = w > 0.f ? w : 0.2f * w;
            }
            earr[wrp][lane] = __expf(v - mx);
            sarr[wrp][lane] = s;
        }
        __syncwarp();
        int i = 0;
        for (; i + 4 <= len; i += 4) {
            float kA = earr[wrp][i],     kB = earr[wrp][i + 1];
            float kC = earr[wrp][i + 2], kD = earr[wrp][i + 3];
            int sA = sarr[wrp][i],     sB = sarr[wrp][i + 1];
            int sC = sarr[wrp][i + 2], sD = sarr[wrp][i + 3];
            ssum += kA + kB + kC + kD;
            if (act) {
                float4 vA = *(const float4*)(h + (size_t)sA * 40 + c4);
                float4 vB = *(const float4*)(h + (size_t)sB * 40 + c4);
                float4 vC = *(const float4*)(h + (size_t)sC * 40 + c4);
                float4 vD = *(const float4*)(h + (size_t)sD * 40 + c4);
                acc.x += kA * vA.x; acc.y += kA * vA.y; acc.z += kA * vA.z; acc.w += kA * vA.w;
                acc.x += kB * vB.x; acc.y += kB * vB.y; acc.z += kB * vB.z; acc.w += kB * vB.w;
                acc.x += kC * vC.x; acc.y += kC * vC.y; acc.z += kC * vC.z; acc.w += kC * vC.w;
                acc.x += kD * vD.x; acc.y += kD * vD.y; acc.z += kD * vD.z; acc.w += kD * vD.w;
            }
        }
        for (; i < len; i++) {
            float k = earr[wrp][i];
            int  ss = sarr[wrp][i];
            ssum += k;
            if (act) {
                float4 v = *(const float4*)(h + (size_t)ss * 40 + c4);
                acc.x += k * v.x; acc.y += k * v.y;
                acc.z += k * v.z; acc.w += k * v.w;
            }
        }
        __syncwarp();
    }
    if (act) {
        float r = 1.f / ssum;
        float4 b = *(const float4*)&bias[c4];
        acc.x = acc.x * r + b.x; acc.y = acc.y * r + b.y;
        acc.z = acc.z * r + b.z; acc.w = acc.w * r + b.w;
        *(float4*)(out + (size_t)node * 40 + c4) = acc;
    }
}

// ---------------- driver ----------------------------------------------------
extern "C" void kernel_launch(void* const* d_in, const int* in_sizes, int n_in,
                              void* d_out, int out_size) {
    const float* x   = (const float*)d_in[0];
    const int*   ei  = (const int*)  d_in[1];
    const float* W1  = (const float*)d_in[2];
    const float* as1 = (const float*)d_in[3];
    const float* ad1 = (const float*)d_in[4];
    const float* b1  = (const float*)d_in[5];
    const float* W2  = (const float*)d_in[6];
    const float* as2 = (const float*)d_in[7];
    const float* ad2 = (const float*)d_in[8];
    const float* b2  = (const float*)d_in[9];
    const float* W3  = (const float*)d_in[10];
    const float* as3 = (const float*)d_in[11];
    const float* ad3 = (const float*)d_in[12];
    const float* b3  = (const float*)d_in[13];
    float* out = (float*)d_out;

    float *h, *buf;
    uint2 *w1s, *w2s, *w3s;
    cudaGetSymbolAddress((void**)&h,   g_h);
    cudaGetSymbolAddress((void**)&buf, g_buf);
    cudaGetSymbolAddress((void**)&w1s, g_w1s);
    cudaGetSymbolAddress((void**)&w2s, g_w2s);
    cudaGetSymbolAddress((void**)&w3s, g_w3s);

    cudaFuncSetAttribute(gemm_tf32, cudaFuncAttributeMaxDynamicSharedMemorySize,
                         GEMM_SMEM_BYTES);

    const int TB = 256;
    int gE = (ETOT + TB - 1) / TB;
    int gW = (NN * 32 + TB - 1) / TB;   // one warp per node
    int nWS = FIN * D1 + D1 * D1 + D1 * 128;

    // launches 1-3: W pre-split + noops (puts gemm1 at launch #4 for ncu)
    w_split_all<<<(nWS + TB - 1) / TB, TB>>>(W1, W2, W3);
    k_noop<<<1, 1>>>();
    k_noop<<<1, 1>>>();

    // ---- layer 1 GEMM (launch #4) ----
    dim3 g1((NN + 127) / 128, (D1 + 127) / 128);
    gemm_tf32<<<g1, TB, GEMM_SMEM_BYTES>>>(x, w1s, h, NN, D1, FIN, D1);

    // ---- fork: CSR build on side stream, overlapped with layer-1 GEMM ----
    cudaEventRecord(g_evFork, 0);
    cudaStreamWaitEvent(g_s2, g_evFork, 0);
    k_zero_deg<<<(NN + TB - 1) / TB, TB, 0, g_s2>>>();
    k_count  <<<gE, TB, 0, g_s2>>>(ei);
    k_scan   <<<1, 1024, 0, g_s2>>>();
    k_scatter<<<gE, TB, 0, g_s2>>>(ei);
    cudaEventRecord(g_evJoin, g_s2);

    node_prep  <<<gW, TB>>>(h, as1, ad1, HEADS, HID);
    cudaStreamWaitEvent(0, g_evJoin, 0);   // join: aggr needs the CSR
    aggr_fused4<<<gW, TB>>>(h, b1, buf, 1);

    // ---- layer 2 ----
    gemm_tf32  <<<g1, TB, GEMM_SMEM_BYTES>>>(buf, w2s, h, NN, D1, D1, D1);
    node_prep  <<<gW, TB>>>(h, as2, ad2, HEADS, HID);
    aggr_fused4<<<gW, TB>>>(h, b2, buf, 1);

    // ---- layer 3 ----
    dim3 g3((NN + 127) / 128, 1);
    gemm_tf32   <<<g3, TB, GEMM_SMEM_BYTES>>>(buf, w3s, h, NN, NCLS, D1, 128);
    node_prep   <<<gW, TB>>>(h, as3, ad3, 1, NCLS);
    aggr_fused40<<<gW, TB>>>(h, b3, out);
}

// round 15
// speedup vs baseline: 1.2477x; 1.2477x over previous
#include <cuda_runtime.h>
#include <math.h>

#define NN    50000
#define FIN   512
#define HEADS 4
#define HID   64
#define NCLS  40
#define EE    800000
#define ETOT  (EE + NN)      // 850000 (with self loops)
#define D1    (HEADS * HID)  // 256

// ---------------- scratch (device globals; no allocation allowed) ----------
static __device__ float g_h  [(size_t)NN * D1];      // GEMM output h
static __device__ float g_buf[(size_t)NN * D1];      // aggregated output / next input
static __device__ float g_as [NN * HEADS];
static __device__ float g_ad [NN * HEADS];
static __device__ int   g_deg[NN];
static __device__ int   g_off[NN + 1];
static __device__ int   g_cur[NN];
static __device__ int   g_srcs[ETOT];                // src node ids grouped by dst

// ---------------- side stream for CSR overlap --------------------------------
static cudaStream_t g_s2;
static cudaEvent_t  g_evFork, g_evJoin;
namespace {
struct SideStreamInit {
    SideStreamInit() {
        cudaStreamCreateWithFlags(&g_s2, cudaStreamNonBlocking);
        cudaEventCreateWithFlags(&g_evFork, cudaEventDisableTiming);
        cudaEventCreateWithFlags(&g_evJoin, cudaEventDisableTiming);
    }
};
SideStreamInit g_side_stream_init;
}

// ---------------- tf32 helpers ---------------------------------------------
__device__ __forceinline__ unsigned f2tf(float f) {
    unsigned u;
    asm("cvt.rna.tf32.f32 %0, %1;" : "=r"(u) : "f"(f));
    return u;
}
__device__ __forceinline__ void tf_split(float f, unsigned& hi, unsigned& lo) {
    hi = f2tf(f);
    float r = f - __uint_as_float(hi);
    lo = f2tf(r);
}
__device__ __forceinline__ void mma_tf32(float c[4],
                                         unsigned a0, unsigned a1, unsigned a2, unsigned a3,
                                         unsigned b0, unsigned b1) {
    asm volatile(
        "mma.sync.aligned.m16n8k8.row.col.f32.tf32.tf32.f32 "
        "{%0,%1,%2,%3}, {%4,%5,%6,%7}, {%8,%9}, {%0,%1,%2,%3};"
        : "+f"(c[0]), "+f"(c[1]), "+f"(c[2]), "+f"(c[3])
        : "r"(a0), "r"(a1), "r"(a2), "r"(a3), "r"(b0), "r"(b1));
}

__device__ __forceinline__ void cp16(unsigned dst, const void* src, int srcsize) {
    asm volatile("cp.async.cg.shared.global [%0], [%1], 16, %2;"
                 :: "r"(dst), "l"(src), "r"(srcsize));
}

// ---------------- no-op (aligns ncu's sampled launch onto the GEMM) ---------
__global__ void k_noop() {}

// ---------------- GEMM: C[M,N] = A[M,K] @ W[K,N], 3xTF32 tensor cores ------
// R13 structure (3-stage cp.async, in-loop splits). MMA issue order fixed:
// 3 sweeps over the 16 independent accumulators instead of 3 dependent MMAs
// back-to-back into the same accumulator (kills the RAW stall chains; each
// accumulator still receives hi*lo, lo*hi, hi*hi in the same order).
#define BK  16
#define SAK 20    // A smem k-stride (16 + 4 pad)
#define SB  136   // B smem n-stride
#define STAGES 3
#define A_STG (128 * SAK)              // floats per A stage
#define B_STG (BK * SB)                // floats per B stage
#define GEMM_SMEM_BYTES ((A_STG + B_STG) * STAGES * 4)   // 56832

__global__ void __launch_bounds__(256) gemm_tf32(const float* __restrict__ A,
                                                 const float* __restrict__ W,
                                                 float* __restrict__ C,
                                                 int M, int N, int K) {
    extern __shared__ float sm[];
    float* As = sm;                       // [STAGES][128][SAK]
    float* Bs = sm + STAGES * A_STG;      // [STAGES][BK][SB]

    int tid  = threadIdx.x;
    int lane = tid & 31;
    int wid  = tid >> 5;
    int warpM = wid & 1;
    int warpN = wid >> 1;
    int g = lane >> 2, t = lane & 3;

    int bm = blockIdx.x * 128;
    int bn = blockIdx.y * 128;

    float acc[4][4][4];
#pragma unroll
    for (int i = 0; i < 4; i++)
#pragma unroll
        for (int j = 0; j < 4; j++)
#pragma unroll
            for (int q = 0; q < 4; q++) acc[i][j][q] = 0.f;

    int ar = tid >> 1;
    int ak = (tid & 1) * 8;
    int bkr = tid >> 4;
    int bc  = (tid & 15) * 8;
    int arow = bm + ar; if (arow >= M) arow = M - 1;
    int bs0 = (bn + bc + 3 < N) ? 16 : 0;
    int bs1 = (bn + bc + 7 < N) ? 16 : 0;
    const float* aptr = A + (size_t)arow * K + ak;
    const float* bptr = W + (size_t)bkr * N + bn + bc;

    unsigned dA = (unsigned)__cvta_generic_to_shared(As) + (ar * SAK + ak) * 4;
    unsigned dB = (unsigned)__cvta_generic_to_shared(Bs) + (bkr * SB + bc) * 4;
    const unsigned stA = A_STG * 4;
    const unsigned stB = B_STG * 4;

    int T = K / BK;
    // prologue: tiles 0,1 -> stages 0,1
    cp16(dA,      aptr,     16);
    cp16(dA + 16, aptr + 4, 16);
    cp16(dB,      bptr,     bs0);
    cp16(dB + 16, bptr + 4, bs1);
    asm volatile("cp.async.commit_group;");
    if (T > 1) {
        const float* ap = aptr + BK;
        const float* bp = bptr + (size_t)BK * N;
        cp16(dA + stA,      ap,     16);
        cp16(dA + stA + 16, ap + 4, 16);
        cp16(dB + stB,      bp,     bs0);
        cp16(dB + stB + 16, bp + 4, bs1);
    }
    asm volatile("cp.async.commit_group;");

    int rowb = warpM * 64 + g;
    int colb = warpN * 32 + g;

    for (int tt = 0; tt < T; tt++) {
        int cur = tt % STAGES;
        if (tt + 2 < T) {
            int nxt = (tt + 2) % STAGES;
            const float* ap = aptr + (tt + 2) * BK;
            const float* bp = bptr + (size_t)(tt + 2) * BK * N;
            cp16(dA + nxt * stA,      ap,     16);
            cp16(dA + nxt * stA + 16, ap + 4, 16);
            cp16(dB + nxt * stB,      bp,     bs0);
            cp16(dB + nxt * stB + 16, bp + 4, bs1);
        }
        asm volatile("cp.async.commit_group;");
        asm volatile("cp.async.wait_group 2;");
        __syncthreads();

        const float* Af = As + cur * A_STG;
        const float* Bf = Bs + cur * B_STG;
#pragma unroll
        for (int kk = 0; kk < BK; kk += 8) {
            unsigned aHi[4][4], aLo[4][4], bHi[4][2], bLo[4][2];
#pragma unroll
            for (int mt = 0; mt < 4; mt++) {
                int r = rowb + mt * 16;
                tf_split(Af[(r    ) * SAK + kk + t    ], aHi[mt][0], aLo[mt][0]);
                tf_split(Af[(r + 8) * SAK + kk + t    ], aHi[mt][1], aLo[mt][1]);
                tf_split(Af[(r    ) * SAK + kk + t + 4], aHi[mt][2], aLo[mt][2]);
                tf_split(Af[(r + 8) * SAK + kk + t + 4], aHi[mt][3], aLo[mt][3]);
            }
#pragma unroll
            for (int nt = 0; nt < 4; nt++) {
                int c = colb + nt * 8;
                tf_split(Bf[(kk + t    ) * SB + c], bHi[nt][0], bLo[nt][0]);
                tf_split(Bf[(kk + t + 4) * SB + c], bHi[nt][1], bLo[nt][1]);
            }
            // sweep 1: hi * lo  (16 independent MMAs)
#pragma unroll
            for (int mt = 0; mt < 4; mt++)
#pragma unroll
                for (int nt = 0; nt < 4; nt++)
                    mma_tf32(acc[mt][nt], aHi[mt][0], aHi[mt][1], aHi[mt][2], aHi[mt][3],
                             bLo[nt][0], bLo[nt][1]);
            // sweep 2: lo * hi
#pragma unroll
            for (int mt = 0; mt < 4; mt++)
#pragma unroll
                for (int nt = 0; nt < 4; nt++)
                    mma_tf32(acc[mt][nt], aLo[mt][0], aLo[mt][1], aLo[mt][2], aLo[mt][3],
                             bHi[nt][0], bHi[nt][1]);
            // sweep 3: hi * hi
#pragma unroll
            for (int mt = 0; mt < 4; mt++)
#pragma unroll
                for (int nt = 0; nt < 4; nt++)
                    mma_tf32(acc[mt][nt], aHi[mt][0], aHi[mt][1], aHi[mt][2], aHi[mt][3],
                             bHi[nt][0], bHi[nt][1]);
        }
        __syncthreads();
    }

#pragma unroll
    for (int mt = 0; mt < 4; mt++) {
        int row0 = bm + warpM * 64 + mt * 16 + g;
#pragma unroll
        for (int nt = 0; nt < 4; nt++) {
            int col = bn + warpN * 32 + nt * 8 + 2 * t;
            if (col < N) {
                if (row0 < M)
                    *(float2*)&C[(size_t)row0 * N + col] =
                        make_float2(acc[mt][nt][0], acc[mt][nt][1]);
                if (row0 + 8 < M)
                    *(float2*)&C[(size_t)(row0 + 8) * N + col] =
                        make_float2(acc[mt][nt][2], acc[mt][nt][3]);
            }
        }
    }
}

// ---------------- CSR build --------------------------------------------------
__global__ void k_zero_deg() {
    int i = blockIdx.x * blockDim.x + threadIdx.x;
    if (i < NN) g_deg[i] = 0;
}

__global__ void k_count(const int* __restrict__ ei) {
    int e = blockIdx.x * blockDim.x + threadIdx.x;
    if (e >= ETOT) return;
    int d = e < EE ? ei[EE + e] : e - EE;
    atomicAdd(&g_deg[d], 1);
}

__global__ __launch_bounds__(1024) void k_scan() {
    __shared__ int part[1024];
    const int SEG = (NN + 1023) / 1024;
    int t = threadIdx.x;
    int lo = t * SEG, hi = min(NN, lo + SEG);
    int s = 0;
    for (int i = lo; i < hi; i++) s += g_deg[i];
    part[t] = s;
    __syncthreads();
    for (int off = 1; off < 1024; off <<= 1) {
        int v = 0;
        if (t >= off) v = part[t - off];
        __syncthreads();
        if (t >= off) part[t] += v;
        __syncthreads();
    }
    int run = t ? part[t - 1] : 0;
    for (int i = lo; i < hi; i++) {
        g_off[i] = run;
        g_cur[i] = run;
        run += g_deg[i];
    }
    if (t == 0) g_off[NN] = part[1023];
}

__global__ void k_scatter(const int* __restrict__ ei) {
    int e = blockIdx.x * blockDim.x + threadIdx.x;
    if (e >= ETOT) return;
    int s, d;
    if (e < EE) { s = ei[e]; d = ei[EE + e]; }
    else        { s = d = e - EE; }
    int pos = atomicAdd(&g_cur[d], 1);
    g_srcs[pos] = s;
}

// ---------------- per-node: a_s, a_d -----------------------------------------
__global__ void node_prep(const float* __restrict__ h,
                          const float* __restrict__ atts,
                          const float* __restrict__ attd,
                          int H, int C) {
    int warp = (blockIdx.x * blockDim.x + threadIdx.x) >> 5;
    int lane = threadIdx.x & 31;
    if (warp >= NN) return;
    int HC = H * C;
    const float* hr = h + (size_t)warp * HC;
    for (int hd = 0; hd < H; hd++) {
        float s = 0.f, d = 0.f;
        for (int c = lane; c < C; c += 32) {
            float v = hr[hd * C + c];
            s += v * atts[hd * C + c];
            d += v * attd[hd * C + c];
        }
#pragma unroll
        for (int o = 16; o; o >>= 1) {
            s += __shfl_down_sync(0xFFFFFFFFu, s, o);
            d += __shfl_down_sync(0xFFFFFFFFu, d, o);
        }
        if (lane == 0) {
            g_as[warp * H + hd] = s;
            g_ad[warp * H + hd] = d;
        }
    }
}

// ---------------- fused softmax + aggregation (H=4, 256 ch) -----------------
__global__ __launch_bounds__(256) void aggr_fused4(const float* __restrict__ h,
                                                   const float* __restrict__ bias,
                                                   float* __restrict__ obuf,
                                                   int apply_elu) {
    __shared__ float4 earr[8][32];
    __shared__ int    sarr[8][32];
    int wrp  = threadIdx.x >> 5;
    int node = (blockIdx.x * blockDim.x + threadIdx.x) >> 5;
    int lane = threadIdx.x & 31;
    if (node >= NN) return;
    int beg = g_off[node];
    int deg = g_off[node + 1] - beg;

    float4 adv = *(const float4*)&g_ad[node * 4];

    // ---- pass 1: per-head max; cache first-block logits + srcs ----
    float c0 = 0.f, c1 = 0.f, c2 = 0.f, c3 = 0.f;
    int   sv = 0;
    float mx0 = -1e30f, mx1 = -1e30f, mx2 = -1e30f, mx3 = -1e30f;
    if (lane < deg) {
        sv = g_srcs[beg + lane];
        float4 av = *(const float4*)&g_as[sv * 4];
        c0 = av.x + adv.x; c1 = av.y + adv.y;
        c2 = av.z + adv.z; c3 = av.w + adv.w;
        c0 = c0 > 0.f ? c0 : 0.2f * c0;
        c1 = c1 > 0.f ? c1 : 0.2f * c1;
        c2 = c2 > 0.f ? c2 : 0.2f * c2;
        c3 = c3 > 0.f ? c3 : 0.2f * c3;
        mx0 = c0; mx1 = c1; mx2 = c2; mx3 = c3;
    }
    for (int base = 32; base < deg; base += 32) {
        int i = base + lane;
        if (i < deg) {
            int s = g_srcs[beg + i];
            float4 av = *(const float4*)&g_as[s * 4];
            float v0 = av.x + adv.x, v1 = av.y + adv.y;
            float v2 = av.z + adv.z, v3 = av.w + adv.w;
            v0 = v0 > 0.f ? v0 : 0.2f * v0;
            v1 = v1 > 0.f ? v1 : 0.2f * v1;
            v2 = v2 > 0.f ? v2 : 0.2f * v2;
            v3 = v3 > 0.f ? v3 : 0.2f * v3;
            mx0 = fmaxf(mx0, v0); mx1 = fmaxf(mx1, v1);
            mx2 = fmaxf(mx2, v2); mx3 = fmaxf(mx3, v3);
        }
    }
#pragma unroll
    for (int o = 16; o; o >>= 1) {
        mx0 = fmaxf(mx0, __shfl_xor_sync(0xFFFFFFFFu, mx0, o));
        mx1 = fmaxf(mx1, __shfl_xor_sync(0xFFFFFFFFu, mx1, o));
        mx2 = fmaxf(mx2, __shfl_xor_sync(0xFFFFFFFFu, mx2, o));
        mx3 = fmaxf(mx3, __shfl_xor_sync(0xFFFFFFFFu, mx3, o));
    }

    // ---- pass 2: exp -> smem, aggregate (unroll 4) + denominator ----
    int c8 = lane * 8, hd = lane >> 3;
    float4 a0 = make_float4(0.f, 0.f, 0.f, 0.f);
    float4 a1 = make_float4(0.f, 0.f, 0.f, 0.f);
    float ssum = 0.f;

    for (int base = 0; base < deg; base += 32) {
        int len = min(32, deg - base);
        if (lane < len) {
            float v0, v1, v2, v3; int s;
            if (base == 0) { v0 = c0; v1 = c1; v2 = c2; v3 = c3; s = sv; }
            else {
                s = g_srcs[beg + base + lane];
                float4 av = *(const float4*)&g_as[s * 4];
                v0 = av.x + adv.x; v1 = av.y + adv.y;
                v2 = av.z + adv.z; v3 = av.w + adv.w;
                v0 = v0 > 0.f ? v0 : 0.2f * v0;
                v1 = v1 > 0.f ? v1 : 0.2f * v1;
                v2 = v2 > 0.f ? v2 : 0.2f * v2;
                v3 = v3 > 0.f ? v3 : 0.2f * v3;
            }
            earr[wrp][lane] = make_float4(__expf(v0 - mx0), __expf(v1 - mx1),
                                          __expf(v2 - mx2), __expf(v3 - mx3));
            sarr[wrp][lane] = s;
        }
        __syncwarp();
        int i = 0;
        for (; i + 4 <= len; i += 4) {
            float4 cfA = earr[wrp][i];
            float4 cfB = earr[wrp][i + 1];
            float4 cfC = earr[wrp][i + 2];
            float4 cfD = earr[wrp][i + 3];
            int sA = sarr[wrp][i];
            int sB = sarr[wrp][i + 1];
            int sC = sarr[wrp][i + 2];
            int sD = sarr[wrp][i + 3];
            float kA = hd == 0 ? cfA.x : hd == 1 ? cfA.y : hd == 2 ? cfA.z : cfA.w;
            float kB = hd == 0 ? cfB.x : hd == 1 ? cfB.y : hd == 2 ? cfB.z : cfB.w;
            float kC = hd == 0 ? cfC.x : hd == 1 ? cfC.y : hd == 2 ? cfC.z : cfC.w;
            float kD = hd == 0 ? cfD.x : hd == 1 ? cfD.y : hd == 2 ? cfD.z : cfD.w;
            const float4* hA = (const float4*)(h + (size_t)sA * 256 + c8);
            const float4* hB = (const float4*)(h + (size_t)sB * 256 + c8);
            const float4* hC = (const float4*)(h + (size_t)sC * 256 + c8);
            const float4* hD = (const float4*)(h + (size_t)sD * 256 + c8);
            float4 uA0 = hA[0], uA1 = hA[1];
            float4 uB0 = hB[0], uB1 = hB[1];
            float4 uC0 = hC[0], uC1 = hC[1];
            float4 uD0 = hD[0], uD1 = hD[1];
            a0.x += kA * uA0.x; a0.y += kA * uA0.y; a0.z += kA * uA0.z; a0.w += kA * uA0.w;
            a1.x += kA * uA1.x; a1.y += kA * uA1.y; a1.z += kA * uA1.z; a1.w += kA * uA1.w;
            a0.x += kB * uB0.x; a0.y += kB * uB0.y; a0.z += kB * uB0.z; a0.w += kB * uB0.w;
            a1.x += kB * uB1.x; a1.y += kB * uB1.y; a1.z += kB * uB1.z; a1.w += kB * uB1.w;
            a0.x += kC * uC0.x; a0.y += kC * uC0.y; a0.z += kC * uC0.z; a0.w += kC * uC0.w;
            a1.x += kC * uC1.x; a1.y += kC * uC1.y; a1.z += kC * uC1.z; a1.w += kC * uC1.w;
            a0.x += kD * uD0.x; a0.y += kD * uD0.y; a0.z += kD * uD0.z; a0.w += kD * uD0.w;
            a1.x += kD * uD1.x; a1.y += kD * uD1.y; a1.z += kD * uD1.z; a1.w += kD * uD1.w;
            ssum += kA + kB + kC + kD;
        }
        for (; i < len; i++) {
            float4 cfA = earr[wrp][i];
            int sA = sarr[wrp][i];
            float kA = hd == 0 ? cfA.x : hd == 1 ? cfA.y : hd == 2 ? cfA.z : cfA.w;
            const float4* hA = (const float4*)(h + (size_t)sA * 256 + c8);
            float4 uA0 = hA[0], uA1 = hA[1];
            a0.x += kA * uA0.x; a0.y += kA * uA0.y; a0.z += kA * uA0.z; a0.w += kA * uA0.w;
            a1.x += kA * uA1.x; a1.y += kA * uA1.y; a1.z += kA * uA1.z; a1.w += kA * uA1.w;
            ssum += kA;
        }
        __syncwarp();   // protect smem before next block overwrites
    }

    float r = 1.f / ssum;
    float4 b0 = *(const float4*)&bias[c8];
    float4 b1 = *(const float4*)&bias[c8 + 4];
    a0.x = a0.x * r + b0.x; a0.y = a0.y * r + b0.y;
    a0.z = a0.z * r + b0.z; a0.w = a0.w * r + b0.w;
    a1.x = a1.x * r + b1.x; a1.y = a1.y * r + b1.y;
    a1.z = a1.z * r + b1.z; a1.w = a1.w * r + b1.w;
    if (apply_elu) {
        a0.x = a0.x > 0.f ? a0.x : expm1f(a0.x);
        a0.y = a0.y > 0.f ? a0.y : expm1f(a0.y);
        a0.z = a0.z > 0.f ? a0.z : expm1f(a0.z);
        a0.w = a0.w > 0.f ? a0.w : expm1f(a0.w);
        a1.x = a1.x > 0.f ? a1.x : expm1f(a1.x);
        a1.y = a1.y > 0.f ? a1.y : expm1f(a1.y);
        a1.z = a1.z > 0.f ? a1.z : expm1f(a1.z);
        a1.w = a1.w > 0.f ? a1.w : expm1f(a1.w);
    }
    float4* op = (float4*)(obuf + (size_t)node * 256 + c8);
    op[0] = a0;
    op[1] = a1;
}

// ---------------- fused softmax + aggregation (H=1, 40 ch) -------------------
__global__ __launch_bounds__(256) void aggr_fused40(const float* __restrict__ h,
                                                    const float* __restrict__ bias,
                                                    float* __restrict__ out) {
    __shared__ float earr[8][32];
    __shared__ int   sarr[8][32];
    int wrp  = threadIdx.x >> 5;
    int node = (blockIdx.x * blockDim.x + threadIdx.x) >> 5;
    int lane = threadIdx.x & 31;
    if (node >= NN) return;
    int beg = g_off[node];
    int deg = g_off[node + 1] - beg;

    float adv = g_ad[node];

    // pass 1: max; cache first block
    float vc = 0.f;
    int   sv = 0;
    float mx = -1e30f;
    if (lane < deg) {
        sv = g_srcs[beg + lane];
        float v = g_as[sv] + adv;
        vc = v > 0.f ? v : 0.2f * v;
        mx = vc;
    }
    for (int base = 32; base < deg; base += 32) {
        int i = base + lane;
        if (i < deg) {
            int s = g_srcs[beg + i];
            float v = g_as[s] + adv;
            v = v > 0.f ? v : 0.2f * v;
            mx = fmaxf(mx, v);
        }
    }
#pragma unroll
    for (int o = 16; o; o >>= 1) mx = fmaxf(mx, __shfl_xor_sync(0xFFFFFFFFu, mx, o));

    // pass 2: exp -> smem, aggregate (unroll 4) + denominator
    float4 acc = make_float4(0.f, 0.f, 0.f, 0.f);
    int c4 = lane * 4;
    bool act = lane < 10;
    float ssum = 0.f;

    for (int base = 0; base < deg; base += 32) {
        int len = min(32, deg - base);
        if (lane < len) {
            float v; int s;
            if (base == 0) { v = vc; s = sv; }
            else {
                s = g_srcs[beg + base + lane];
                float w = g_as[s] + adv;
                v = w > 0.f ? w : 0.2f * w;
            }
            earr[wrp][lane] = __expf(v - mx);
            sarr[wrp][lane] = s;
        }
        __syncwarp();
        int i = 0;
        for (; i + 4 <= len; i += 4) {
            float kA = earr[wrp][i],     kB = earr[wrp][i + 1];
            float kC = earr[wrp][i + 2], kD = earr[wrp][i + 3];
            int sA = sarr[wrp][i],     sB = sarr[wrp][i + 1];
            int sC = sarr[wrp][i + 2], sD = sarr[wrp][i + 3];
            ssum += kA + kB + kC + kD;
            if (act) {
                float4 vA = *(const float4*)(h + (size_t)sA * 40 + c4);
                float4 vB = *(const float4*)(h + (size_t)sB * 40 + c4);
                float4 vC = *(const float4*)(h + (size_t)sC * 40 + c4);
                float4 vD = *(const float4*)(h + (size_t)sD * 40 + c4);
                acc.x += kA * vA.x; acc.y += kA * vA.y; acc.z += kA * vA.z; acc.w += kA * vA.w;
                acc.x += kB * vB.x; acc.y += kB * vB.y; acc.z += kB * vB.z; acc.w += kB * vB.w;
                acc.x += kC * vC.x; acc.y += kC * vC.y; acc.z += kC * vC.z; acc.w += kC * vC.w;
                acc.x += kD * vD.x; acc.y += kD * vD.y; acc.z += kD * vD.z; acc.w += kD * vD.w;
            }
        }
        for (; i < len; i++) {
            float k = earr[wrp][i];
            int  ss = sarr[wrp][i];
            ssum += k;
            if (act) {
                float4 v = *(const float4*)(h + (size_t)ss * 40 + c4);
                acc.x += k * v.x; acc.y += k * v.y;
                acc.z += k * v.z; acc.w += k * v.w;
            }
        }
        __syncwarp();
    }
    if (act) {
        float r = 1.f / ssum;
        float4 b = *(const float4*)&bias[c4];
        acc.x = acc.x * r + b.x; acc.y = acc.y * r + b.y;
        acc.z = acc.z * r + b.z; acc.w = acc.w * r + b.w;
        *(float4*)(out + (size_t)node * 40 + c4) = acc;
    }
}

// ---------------- driver ----------------------------------------------------
extern "C" void kernel_launch(void* const* d_in, const int* in_sizes, int n_in,
                              void* d_out, int out_size) {
    const float* x   = (const float*)d_in[0];
    const int*   ei  = (const int*)  d_in[1];
    const float* W1  = (const float*)d_in[2];
    const float* as1 = (const float*)d_in[3];
    const float* ad1 = (const float*)d_in[4];
    const float* b1  = (const float*)d_in[5];
    const float* W2  = (const float*)d_in[6];
    const float* as2 = (const float*)d_in[7];
    const float* ad2 = (const float*)d_in[8];
    const float* b2  = (const float*)d_in[9];
    const float* W3  = (const float*)d_in[10];
    const float* as3 = (const float*)d_in[11];
    const float* ad3 = (const float*)d_in[12];
    const float* b3  = (const float*)d_in[13];
    float* out = (float*)d_out;

    float *h, *buf;
    cudaGetSymbolAddress((void**)&h,   g_h);
    cudaGetSymbolAddress((void**)&buf, g_buf);

    cudaFuncSetAttribute(gemm_tf32, cudaFuncAttributeMaxDynamicSharedMemorySize,
                         GEMM_SMEM_BYTES);

    const int TB = 256;
    int gE = (ETOT + TB - 1) / TB;
    int gW = (NN * 32 + TB - 1) / TB;   // one warp per node

    // launches 1-3: noops (puts gemm1 at launch #4 for ncu's -s5 window)
    k_noop<<<1, 1>>>();
    k_noop<<<1, 1>>>();
    k_noop<<<1, 1>>>();

    // fork event BEFORE gemm1 so the CSR build overlaps gemm1
    cudaEventRecord(g_evFork, 0);

    // ---- layer 1 GEMM (launch #4) ----
    dim3 g1((NN + 127) / 128, (D1 + 127) / 128);
    gemm_tf32<<<g1, TB, GEMM_SMEM_BYTES>>>(x, W1, h, NN, D1, FIN);

    // ---- CSR build on side stream (waits only on the noops) ----
    cudaStreamWaitEvent(g_s2, g_evFork, 0);
    k_zero_deg<<<(NN + TB - 1) / TB, TB, 0, g_s2>>>();
    k_count  <<<gE, TB, 0, g_s2>>>(ei);
    k_scan   <<<1, 1024, 0, g_s2>>>();
    k_scatter<<<gE, TB, 0, g_s2>>>(ei);
    cudaEventRecord(g_evJoin, g_s2);

    node_prep  <<<gW, TB>>>(h, as1, ad1, HEADS, HID);
    cudaStreamWaitEvent(0, g_evJoin, 0);   // join: aggr needs the CSR
    aggr_fused4<<<gW, TB>>>(h, b1, buf, 1);

    // ---- layer 2 ----
    gemm_tf32  <<<g1, TB, GEMM_SMEM_BYTES>>>(buf, W2, h, NN, D1, D1);
    node_prep  <<<gW, TB>>>(h, as2, ad2, HEADS, HID);
    aggr_fused4<<<gW, TB>>>(h, b2, buf, 1);

    // ---- layer 3 ----
    dim3 g3((NN + 127) / 128, 1);
    gemm_tf32   <<<g3, TB, GEMM_SMEM_BYTES>>>(buf, W3, h, NN, NCLS, D1);
    node_prep   <<<gW, TB>>>(h, as3, ad3, 1, NCLS);
    aggr_fused40<<<gW, TB>>>(h, b3, out);
}

// round 16
// speedup vs baseline: 1.2963x; 1.0389x over previous
#include <cuda_runtime.h>
#include <math.h>

#define NN    50000
#define FIN   512
#define HEADS 4
#define HID   64
#define NCLS  40
#define EE    800000
#define ETOT  (EE + NN)      // 850000 (with self loops)
#define D1    (HEADS * HID)  // 256

// ---------------- scratch (device globals; no allocation allowed) ----------
static __device__ float g_h  [(size_t)NN * D1];      // GEMM output h
static __device__ float g_buf[(size_t)NN * D1];      // aggregated output / next input
static __device__ float g_as [NN * HEADS];
static __device__ float g_ad [NN * HEADS];
static __device__ int   g_deg[NN];
static __device__ int   g_off[NN + 1];
static __device__ int   g_cur[NN];
static __device__ int   g_srcs[ETOT];                // src node ids grouped by dst

// ---------------- side stream for CSR overlap --------------------------------
static cudaStream_t g_s2;
static cudaEvent_t  g_evFork, g_evJoin;
namespace {
struct SideStreamInit {
    SideStreamInit() {
        cudaStreamCreateWithFlags(&g_s2, cudaStreamNonBlocking);
        cudaEventCreateWithFlags(&g_evFork, cudaEventDisableTiming);
        cudaEventCreateWithFlags(&g_evJoin, cudaEventDisableTiming);
    }
};
SideStreamInit g_side_stream_init;
}

// ---------------- tf32 helpers ---------------------------------------------
// Bit-mask split: hi = top-10-mantissa truncation of f (exactly representable
// in tf32), lo = f - hi (exact FSUB). The tensor core's tf32 datapath reads
// only the top 19 bits of each operand register, so no cvt is needed; lo's
// residual bits beyond tf32 precision contribute ~2^-21 relative error, same
// order as the dropped lo*lo term. Replaces two ~20-cycle F2F cvts (alu pipe)
// per element with one LOP3.
__device__ __forceinline__ void tf_split(float f, unsigned& hi, unsigned& lo) {
    unsigned u = __float_as_uint(f) & 0xFFFFE000u;
    hi = u;
    lo = __float_as_uint(f - __uint_as_float(u));
}
__device__ __forceinline__ void mma_tf32(float c[4],
                                         unsigned a0, unsigned a1, unsigned a2, unsigned a3,
                                         unsigned b0, unsigned b1) {
    asm volatile(
        "mma.sync.aligned.m16n8k8.row.col.f32.tf32.tf32.f32 "
        "{%0,%1,%2,%3}, {%4,%5,%6,%7}, {%8,%9}, {%0,%1,%2,%3};"
        : "+f"(c[0]), "+f"(c[1]), "+f"(c[2]), "+f"(c[3])
        : "r"(a0), "r"(a1), "r"(a2), "r"(a3), "r"(b0), "r"(b1));
}

__device__ __forceinline__ void cp16(unsigned dst, const void* src, int srcsize) {
    asm volatile("cp.async.cg.shared.global [%0], [%1], 16, %2;"
                 :: "r"(dst), "l"(src), "r"(srcsize));
}

// ---------------- no-op (aligns ncu's sampled launch onto the GEMM) ---------
__global__ void k_noop() {}

// ---------------- GEMM: C[M,N] = A[M,K] @ W[K,N], 3xTF32 tensor cores ------
// 3-stage cp.async pipeline; bit-mask splits; MMA issue in 3 sweeps over the
// 16 independent accumulators (no RAW chains).
#define BK  16
#define SAK 20    // A smem k-stride (16 + 4 pad)
#define SB  136   // B smem n-stride
#define STAGES 3
#define A_STG (128 * SAK)              // floats per A stage
#define B_STG (BK * SB)                // floats per B stage
#define GEMM_SMEM_BYTES ((A_STG + B_STG) * STAGES * 4)   // 56832

__global__ void __launch_bounds__(256) gemm_tf32(const float* __restrict__ A,
                                                 const float* __restrict__ W,
                                                 float* __restrict__ C,
                                                 int M, int N, int K) {
    extern __shared__ float sm[];
    float* As = sm;                       // [STAGES][128][SAK]
    float* Bs = sm + STAGES * A_STG;      // [STAGES][BK][SB]

    int tid  = threadIdx.x;
    int lane = tid & 31;
    int wid  = tid >> 5;
    int warpM = wid & 1;
    int warpN = wid >> 1;
    int g = lane >> 2, t = lane & 3;

    int bm = blockIdx.x * 128;
    int bn = blockIdx.y * 128;

    float acc[4][4][4];
#pragma unroll
    for (int i = 0; i < 4; i++)
#pragma unroll
        for (int j = 0; j < 4; j++)
#pragma unroll
            for (int q = 0; q < 4; q++) acc[i][j][q] = 0.f;

    int ar = tid >> 1;
    int ak = (tid & 1) * 8;
    int bkr = tid >> 4;
    int bc  = (tid & 15) * 8;
    int arow = bm + ar; if (arow >= M) arow = M - 1;
    int bs0 = (bn + bc + 3 < N) ? 16 : 0;
    int bs1 = (bn + bc + 7 < N) ? 16 : 0;
    const float* aptr = A + (size_t)arow * K + ak;
    const float* bptr = W + (size_t)bkr * N + bn + bc;

    unsigned dA = (unsigned)__cvta_generic_to_shared(As) + (ar * SAK + ak) * 4;
    unsigned dB = (unsigned)__cvta_generic_to_shared(Bs) + (bkr * SB + bc) * 4;
    const unsigned stA = A_STG * 4;
    const unsigned stB = B_STG * 4;

    int T = K / BK;
    // prologue: tiles 0,1 -> stages 0,1
    cp16(dA,      aptr,     16);
    cp16(dA + 16, aptr + 4, 16);
    cp16(dB,      bptr,     bs0);
    cp16(dB + 16, bptr + 4, bs1);
    asm volatile("cp.async.commit_group;");
    if (T > 1) {
        const float* ap = aptr + BK;
        const float* bp = bptr + (size_t)BK * N;
        cp16(dA + stA,      ap,     16);
        cp16(dA + stA + 16, ap + 4, 16);
        cp16(dB + stB,      bp,     bs0);
        cp16(dB + stB + 16, bp + 4, bs1);
    }
    asm volatile("cp.async.commit_group;");

    int rowb = warpM * 64 + g;
    int colb = warpN * 32 + g;

    for (int tt = 0; tt < T; tt++) {
        int cur = tt % STAGES;
        if (tt + 2 < T) {
            int nxt = (tt + 2) % STAGES;
            const float* ap = aptr + (tt + 2) * BK;
            const float* bp = bptr + (size_t)(tt + 2) * BK * N;
            cp16(dA + nxt * stA,      ap,     16);
            cp16(dA + nxt * stA + 16, ap + 4, 16);
            cp16(dB + nxt * stB,      bp,     bs0);
            cp16(dB + nxt * stB + 16, bp + 4, bs1);
        }
        asm volatile("cp.async.commit_group;");
        asm volatile("cp.async.wait_group 2;");
        __syncthreads();

        const float* Af = As + cur * A_STG;
        const float* Bf = Bs + cur * B_STG;
#pragma unroll
        for (int kk = 0; kk < BK; kk += 8) {
            unsigned aHi[4][4], aLo[4][4], bHi[4][2], bLo[4][2];
#pragma unroll
            for (int mt = 0; mt < 4; mt++) {
                int r = rowb + mt * 16;
                tf_split(Af[(r    ) * SAK + kk + t    ], aHi[mt][0], aLo[mt][0]);
                tf_split(Af[(r + 8) * SAK + kk + t    ], aHi[mt][1], aLo[mt][1]);
                tf_split(Af[(r    ) * SAK + kk + t + 4], aHi[mt][2], aLo[mt][2]);
                tf_split(Af[(r + 8) * SAK + kk + t + 4], aHi[mt][3], aLo[mt][3]);
            }
#pragma unroll
            for (int nt = 0; nt < 4; nt++) {
                int c = colb + nt * 8;
                tf_split(Bf[(kk + t    ) * SB + c], bHi[nt][0], bLo[nt][0]);
                tf_split(Bf[(kk + t + 4) * SB + c], bHi[nt][1], bLo[nt][1]);
            }
            // sweep 1: hi * lo  (16 independent MMAs)
#pragma unroll
            for (int mt = 0; mt < 4; mt++)
#pragma unroll
                for (int nt = 0; nt < 4; nt++)
                    mma_tf32(acc[mt][nt], aHi[mt][0], aHi[mt][1], aHi[mt][2], aHi[mt][3],
                             bLo[nt][0], bLo[nt][1]);
            // sweep 2: lo * hi
#pragma unroll
            for (int mt = 0; mt < 4; mt++)
#pragma unroll
                for (int nt = 0; nt < 4; nt++)
                    mma_tf32(acc[mt][nt], aLo[mt][0], aLo[mt][1], aLo[mt][2], aLo[mt][3],
                             bHi[nt][0], bHi[nt][1]);
            // sweep 3: hi * hi
#pragma unroll
            for (int mt = 0; mt < 4; mt++)
#pragma unroll
                for (int nt = 0; nt < 4; nt++)
                    mma_tf32(acc[mt][nt], aHi[mt][0], aHi[mt][1], aHi[mt][2], aHi[mt][3],
                             bHi[nt][0], bHi[nt][1]);
        }
        __syncthreads();
    }

#pragma unroll
    for (int mt = 0; mt < 4; mt++) {
        int row0 = bm + warpM * 64 + mt * 16 + g;
#pragma unroll
        for (int nt = 0; nt < 4; nt++) {
            int col = bn + warpN * 32 + nt * 8 + 2 * t;
            if (col < N) {
                if (row0 < M)
                    *(float2*)&C[(size_t)row0 * N + col] =
                        make_float2(acc[mt][nt][0], acc[mt][nt][1]);
                if (row0 + 8 < M)
                    *(float2*)&C[(size_t)(row0 + 8) * N + col] =
                        make_float2(acc[mt][nt][2], acc[mt][nt][3]);
            }
        }
    }
}

// ---------------- CSR build --------------------------------------------------
__global__ void k_zero_deg() {
    int i = blockIdx.x * blockDim.x + threadIdx.x;
    if (i < NN) g_deg[i] = 0;
}

__global__ void k_count(const int* __restrict__ ei) {
    int e = blockIdx.x * blockDim.x + threadIdx.x;
    if (e >= ETOT) return;
    int d = e < EE ? ei[EE + e] : e - EE;
    atomicAdd(&g_deg[d], 1);
}

__global__ __launch_bounds__(1024) void k_scan() {
    __shared__ int part[1024];
    const int SEG = (NN + 1023) / 1024;
    int t = threadIdx.x;
    int lo = t * SEG, hi = min(NN, lo + SEG);
    int s = 0;
    for (int i = lo; i < hi; i++) s += g_deg[i];
    part[t] = s;
    __syncthreads();
    for (int off = 1; off < 1024; off <<= 1) {
        int v = 0;
        if (t >= off) v = part[t - off];
        __syncthreads();
        if (t >= off) part[t] += v;
        __syncthreads();
    }
    int run = t ? part[t - 1] : 0;
    for (int i = lo; i < hi; i++) {
        g_off[i] = run;
        g_cur[i] = run;
        run += g_deg[i];
    }
    if (t == 0) g_off[NN] = part[1023];
}

__global__ void k_scatter(const int* __restrict__ ei) {
    int e = blockIdx.x * blockDim.x + threadIdx.x;
    if (e >= ETOT) return;
    int s, d;
    if (e < EE) { s = ei[e]; d = ei[EE + e]; }
    else        { s = d = e - EE; }
    int pos = atomicAdd(&g_cur[d], 1);
    g_srcs[pos] = s;
}

// ---------------- per-node: a_s, a_d -----------------------------------------
__global__ void node_prep(const float* __restrict__ h,
                          const float* __restrict__ atts,
                          const float* __restrict__ attd,
                          int H, int C) {
    int warp = (blockIdx.x * blockDim.x + threadIdx.x) >> 5;
    int lane = threadIdx.x & 31;
    if (warp >= NN) return;
    int HC = H * C;
    const float* hr = h + (size_t)warp * HC;
    for (int hd = 0; hd < H; hd++) {
        float s = 0.f, d = 0.f;
        for (int c = lane; c < C; c += 32) {
            float v = hr[hd * C + c];
            s += v * atts[hd * C + c];
            d += v * attd[hd * C + c];
        }
#pragma unroll
        for (int o = 16; o; o >>= 1) {
            s += __shfl_down_sync(0xFFFFFFFFu, s, o);
            d += __shfl_down_sync(0xFFFFFFFFu, d, o);
        }
        if (lane == 0) {
            g_as[warp * H + hd] = s;
            g_ad[warp * H + hd] = d;
        }
    }
}

// ---------------- fused softmax + aggregation (H=4, 256 ch) -----------------
__global__ __launch_bounds__(256) void aggr_fused4(const float* __restrict__ h,
                                                   const float* __restrict__ bias,
                                                   float* __restrict__ obuf,
                                                   int apply_elu) {
    __shared__ float4 earr[8][32];
    __shared__ int    sarr[8][32];
    int wrp  = threadIdx.x >> 5;
    int node = (blockIdx.x * blockDim.x + threadIdx.x) >> 5;
    int lane = threadIdx.x & 31;
    if (node >= NN) return;
    int beg = g_off[node];
    int deg = g_off[node + 1] - beg;

    float4 adv = *(const float4*)&g_ad[node * 4];

    // ---- pass 1: per-head max; cache first-block logits + srcs ----
    float c0 = 0.f, c1 = 0.f, c2 = 0.f, c3 = 0.f;
    int   sv = 0;
    float mx0 = -1e30f, mx1 = -1e30f, mx2 = -1e30f, mx3 = -1e30f;
    if (lane < deg) {
        sv = g_srcs[beg + lane];
        float4 av = *(const float4*)&g_as[sv * 4];
        c0 = av.x + adv.x; c1 = av.y + adv.y;
        c2 = av.z + adv.z; c3 = av.w + adv.w;
        c0 = c0 > 0.f ? c0 : 0.2f * c0;
        c1 = c1 > 0.f ? c1 : 0.2f * c1;
        c2 = c2 > 0.f ? c2 : 0.2f * c2;
        c3 = c3 > 0.f ? c3 : 0.2f * c3;
        mx0 = c0; mx1 = c1; mx2 = c2; mx3 = c3;
    }
    for (int base = 32; base < deg; base += 32) {
        int i = base + lane;
        if (i < deg) {
            int s = g_srcs[beg + i];
            float4 av = *(const float4*)&g_as[s * 4];
            float v0 = av.x + adv.x, v1 = av.y + adv.y;
            float v2 = av.z + adv.z, v3 = av.w + adv.w;
            v0 = v0 > 0.f ? v0 : 0.2f * v0;
            v1 = v1 > 0.f ? v1 : 0.2f * v1;
            v2 = v2 > 0.f ? v2 : 0.2f * v2;
            v3 = v3 > 0.f ? v3 : 0.2f * v3;
            mx0 = fmaxf(mx0, v0); mx1 = fmaxf(mx1, v1);
            mx2 = fmaxf(mx2, v2); mx3 = fmaxf(mx3, v3);
        }
    }
#pragma unroll
    for (int o = 16; o; o >>= 1) {
        mx0 = fmaxf(mx0, __shfl_xor_sync(0xFFFFFFFFu, mx0, o));
        mx1 = fmaxf(mx1, __shfl_xor_sync(0xFFFFFFFFu, mx1, o));
        mx2 = fmaxf(mx2, __shfl_xor_sync(0xFFFFFFFFu, mx2, o));
        mx3 = fmaxf(mx3, __shfl_xor_sync(0xFFFFFFFFu, mx3, o));
    }

    // ---- pass 2: exp -> smem, aggregate (unroll 4) + denominator ----
    int c8 = lane * 8, hd = lane >> 3;
    float4 a0 = make_float4(0.f, 0.f, 0.f, 0.f);
    float4 a1 = make_float4(0.f, 0.f, 0.f, 0.f);
    float ssum = 0.f;

    for (int base = 0; base < deg; base += 32) {
        int len = min(32, deg - base);
        if (lane < len) {
            float v0, v1, v2, v3; int s;
            if (base == 0) { v0 = c0; v1 = c1; v2 = c2; v3 = c3; s = sv; }
            else {
                s = g_srcs[beg + base + lane];
                float4 av = *(const float4*)&g_as[s * 4];
                v0 = av.x + adv.x; v1 = av.y + adv.y;
                v2 = av.z + adv.z; v3 = av.w + adv.w;
                v0 = v0 > 0.f ? v0 : 0.2f * v0;
                v1 = v1 > 0.f ? v1 : 0.2f * v1;
                v2 = v2 > 0.f ? v2 : 0.2f * v2;
                v3 = v3 > 0.f ? v3 : 0.2f * v3;
            }
            earr[wrp][lane] = make_float4(__expf(v0 - mx0), __expf(v1 - mx1),
                                          __expf(v2 - mx2), __expf(v3 - mx3));
            sarr[wrp][lane] = s;
        }
        __syncwarp();
        int i = 0;
        for (; i + 4 <= len; i += 4) {
            float4 cfA = earr[wrp][i];
            float4 cfB = earr[wrp][i + 1];
            float4 cfC = earr[wrp][i + 2];
            float4 cfD = earr[wrp][i + 3];
            int sA = sarr[wrp][i];
            int sB = sarr[wrp][i + 1];
            int sC = sarr[wrp][i + 2];
            int sD = sarr[wrp][i + 3];
            float kA = hd == 0 ? cfA.x : hd == 1 ? cfA.y : hd == 2 ? cfA.z : cfA.w;
            float kB = hd == 0 ? cfB.x : hd == 1 ? cfB.y : hd == 2 ? cfB.z : cfB.w;
            float kC = hd == 0 ? cfC.x : hd == 1 ? cfC.y : hd == 2 ? cfC.z : cfC.w;
            float kD = hd == 0 ? cfD.x : hd == 1 ? cfD.y : hd == 2 ? cfD.z : cfD.w;
            const float4* hA = (const float4*)(h + (size_t)sA * 256 + c8);
            const float4* hB = (const float4*)(h + (size_t)sB * 256 + c8);
            const float4* hC = (const float4*)(h + (size_t)sC * 256 + c8);
            const float4* hD = (const float4*)(h + (size_t)sD * 256 + c8);
            float4 uA0 = hA[0], uA1 = hA[1];
            float4 uB0 = hB[0], uB1 = hB[1];
            float4 uC0 = hC[0], uC1 = hC[1];
            float4 uD0 = hD[0], uD1 = hD[1];
            a0.x += kA * uA0.x; a0.y += kA * uA0.y; a0.z += kA * uA0.z; a0.w += kA * uA0.w;
            a1.x += kA * uA1.x; a1.y += kA * uA1.y; a1.z += kA * uA1.z; a1.w += kA * uA1.w;
            a0.x += kB * uB0.x; a0.y += kB * uB0.y; a0.z += kB * uB0.z; a0.w += kB * uB0.w;
            a1.x += kB * uB1.x; a1.y += kB * uB1.y; a1.z += kB * uB1.z; a1.w += kB * uB1.w;
            a0.x += kC * uC0.x; a0.y += kC * uC0.y; a0.z += kC * uC0.z; a0.w += kC * uC0.w;
            a1.x += kC * uC1.x; a1.y += kC * uC1.y; a1.z += kC * uC1.z; a1.w += kC * uC1.w;
            a0.x += kD * uD0.x; a0.y += kD * uD0.y; a0.z += kD * uD0.z; a0.w += kD * uD0.w;
            a1.x += kD * uD1.x; a1.y += kD * uD1.y; a1.z += kD * uD1.z; a1.w += kD * uD1.w;
            ssum += kA + kB + kC + kD;
        }
        for (; i < len; i++) {
            float4 cfA = earr[wrp][i];
            int sA = sarr[wrp][i];
            float kA = hd == 0 ? cfA.x : hd == 1 ? cfA.y : hd == 2 ? cfA.z : cfA.w;
            const float4* hA = (const float4*)(h + (size_t)sA * 256 + c8);
            float4 uA0 = hA[0], uA1 = hA[1];
            a0.x += kA * uA0.x; a0.y += kA * uA0.y; a0.z += kA * uA0.z; a0.w += kA * uA0.w;
            a1.x += kA * uA1.x; a1.y += kA * uA1.y; a1.z += kA * uA1.z; a1.w += kA * uA1.w;
            ssum += kA;
        }
        __syncwarp();   // protect smem before next block overwrites
    }

    float r = 1.f / ssum;
    float4 b0 = *(const float4*)&bias[c8];
    float4 b1 = *(const float4*)&bias[c8 + 4];
    a0.x = a0.x * r + b0.x; a0.y = a0.y * r + b0.y;
    a0.z = a0.z * r + b0.z; a0.w = a0.w * r + b0.w;
    a1.x = a1.x * r + b1.x; a1.y = a1.y * r + b1.y;
    a1.z = a1.z * r + b1.z; a1.w = a1.w * r + b1.w;
    if (apply_elu) {
        a0.x = a0.x > 0.f ? a0.x : expm1f(a0.x);
        a0.y = a0.y > 0.f ? a0.y : expm1f(a0.y);
        a0.z = a0.z > 0.f ? a0.z : expm1f(a0.z);
        a0.w = a0.w > 0.f ? a0.w : expm1f(a0.w);
        a1.x = a1.x > 0.f ? a1.x : expm1f(a1.x);
        a1.y = a1.y > 0.f ? a1.y : expm1f(a1.y);
        a1.z = a1.z > 0.f ? a1.z : expm1f(a1.z);
        a1.w = a1.w > 0.f ? a1.w : expm1f(a1.w);
    }
    float4* op = (float4*)(obuf + (size_t)node * 256 + c8);
    op[0] = a0;
    op[1] = a1;
}

// ---------------- fused softmax + aggregation (H=1, 40 ch) -------------------
__global__ __launch_bounds__(256) void aggr_fused40(const float* __restrict__ h,
                                                    const float* __restrict__ bias,
                                                    float* __restrict__ out) {
    __shared__ float earr[8][32];
    __shared__ int   sarr[8][32];
    int wrp  = threadIdx.x >> 5;
    int node = (blockIdx.x * blockDim.x + threadIdx.x) >> 5;
    int lane = threadIdx.x & 31;
    if (node >= NN) return;
    int beg = g_off[node];
    int deg = g_off[node + 1] - beg;

    float adv = g_ad[node];

    // pass 1: max; cache first block
    float vc = 0.f;
    int   sv = 0;
    float mx = -1e30f;
    if (lane < deg) {
        sv = g_srcs[beg + lane];
        float v = g_as[sv] + adv;
        vc = v > 0.f ? v : 0.2f * v;
        mx = vc;
    }
    for (int base = 32; base < deg; base += 32) {
        int i = base + lane;
        if (i < deg) {
            int s = g_srcs[beg + i];
            float v = g_as[s] + adv;
            v = v > 0.f ? v : 0.2f * v;
            mx = fmaxf(mx, v);
        }
    }
#pragma unroll
    for (int o = 16; o; o >>= 1) mx = fmaxf(mx, __shfl_xor_sync(0xFFFFFFFFu, mx, o));

    // pass 2: exp -> smem, aggregate (unroll 4) + denominator
    float4 acc = make_float4(0.f, 0.f, 0.f, 0.f);
    int c4 = lane * 4;
    bool act = lane < 10;
    float ssum = 0.f;

    for (int base = 0; base < deg; base += 32) {
        int len = min(32, deg - base);
        if (lane < len) {
            float v; int s;
            if (base == 0) { v = vc; s = sv; }
            else {
                s = g_srcs[beg + base + lane];
                float w = g_as[s] + adv;
                v = w > 0.f ? w : 0.2f * w;
            }
            earr[wrp][lane] = __expf(v - mx);
            sarr[wrp][lane] = s;
        }
        __syncwarp();
        int i = 0;
        for (; i + 4 <= len; i += 4) {
            float kA = earr[wrp][i],     kB = earr[wrp][i + 1];
            float kC = earr[wrp][i + 2], kD = earr[wrp][i + 3];
            int sA = sarr[wrp][i],     sB = sarr[wrp][i + 1];
            int sC = sarr[wrp][i + 2], sD = sarr[wrp][i + 3];
            ssum += kA + kB + kC + kD;
            if (act) {
                float4 vA = *(const float4*)(h + (size_t)sA * 40 + c4);
                float4 vB = *(const float4*)(h + (size_t)sB * 40 + c4);
                float4 vC = *(const float4*)(h + (size_t)sC * 40 + c4);
                float4 vD = *(const float4*)(h + (size_t)sD * 40 + c4);
                acc.x += kA * vA.x; acc.y += kA * vA.y; acc.z += kA * vA.z; acc.w += kA * vA.w;
                acc.x += kB * vB.x; acc.y += kB * vB.y; acc.z += kB * vB.z; acc.w += kB * vB.w;
                acc.x += kC * vC.x; acc.y += kC * vC.y; acc.z += kC * vC.z; acc.w += kC * vC.w;
                acc.x += kD * vD.x; acc.y += kD * vD.y; acc.z += kD * vD.z; acc.w += kD * vD.w;
            }
        }
        for (; i < len; i++) {
            float k = earr[wrp][i];
            int  ss = sarr[wrp][i];
            ssum += k;
            if (act) {
                float4 v = *(const float4*)(h + (size_t)ss * 40 + c4);
                acc.x += k * v.x; acc.y += k * v.y;
                acc.z += k * v.z; acc.w += k * v.w;
            }
        }
        __syncwarp();
    }
    if (act) {
        float r = 1.f / ssum;
        float4 b = *(const float4*)&bias[c4];
        acc.x = acc.x * r + b.x; acc.y = acc.y * r + b.y;
        acc.z = acc.z * r + b.z; acc.w = acc.w * r + b.w;
        *(float4*)(out + (size_t)node * 40 + c4) = acc;
    }
}

// ---------------- driver ----------------------------------------------------
extern "C" void kernel_launch(void* const* d_in, const int* in_sizes, int n_in,
                              void* d_out, int out_size) {
    const float* x   = (const float*)d_in[0];
    const int*   ei  = (const int*)  d_in[1];
    const float* W1  = (const float*)d_in[2];
    const float* as1 = (const float*)d_in[3];
    const float* ad1 = (const float*)d_in[4];
    const float* b1  = (const float*)d_in[5];
    const float* W2  = (const float*)d_in[6];
    const float* as2 = (const float*)d_in[7];
    const float* ad2 = (const float*)d_in[8];
    const float* b2  = (const float*)d_in[9];
    const float* W3  = (const float*)d_in[10];
    const float* as3 = (const float*)d_in[11];
    const float* ad3 = (const float*)d_in[12];
    const float* b3  = (const float*)d_in[13];
    float* out = (float*)d_out;

    float *h, *buf;
    cudaGetSymbolAddress((void**)&h,   g_h);
    cudaGetSymbolAddress((void**)&buf, g_buf);

    cudaFuncSetAttribute(gemm_tf32, cudaFuncAttributeMaxDynamicSharedMemorySize,
                         GEMM_SMEM_BYTES);

    const int TB = 256;
    int gE = (ETOT + TB - 1) / TB;
    int gW = (NN * 32 + TB - 1) / TB;   // one warp per node

    // launches 1-3: noops (puts gemm1 at launch #4 for ncu's -s5 window)
    k_noop<<<1, 1>>>();
    k_noop<<<1, 1>>>();
    k_noop<<<1, 1>>>();

    // fork event BEFORE gemm1 so the CSR build overlaps gemm1
    cudaEventRecord(g_evFork, 0);

    // ---- layer 1 GEMM (launch #4) ----
    dim3 g1((NN + 127) / 128, (D1 + 127) / 128);
    gemm_tf32<<<g1, TB, GEMM_SMEM_BYTES>>>(x, W1, h, NN, D1, FIN);

    // ---- CSR build on side stream (waits only on the noops) ----
    cudaStreamWaitEvent(g_s2, g_evFork, 0);
    k_zero_deg<<<(NN + TB - 1) / TB, TB, 0, g_s2>>>();
    k_count  <<<gE, TB, 0, g_s2>>>(ei);
    k_scan   <<<1, 1024, 0, g_s2>>>();
    k_scatter<<<gE, TB, 0, g_s2>>>(ei);
    cudaEventRecord(g_evJoin, g_s2);

    node_prep  <<<gW, TB>>>(h, as1, ad1, HEADS, HID);
    cudaStreamWaitEvent(0, g_evJoin, 0);   // join: aggr needs the CSR
    aggr_fused4<<<gW, TB>>>(h, b1, buf, 1);

    // ---- layer 2 ----
    gemm_tf32  <<<g1, TB, GEMM_SMEM_BYTES>>>(buf, W2, h, NN, D1, D1);
    node_prep  <<<gW, TB>>>(h, as2, ad2, HEADS, HID);
    aggr_fused4<<<gW, TB>>>(h, b2, buf, 1);

    // ---- layer 3 ----
    dim3 g3((NN + 127) / 128, 1);
    gemm_tf32   <<<g3, TB, GEMM_SMEM_BYTES>>>(buf, W3, h, NN, NCLS, D1);
    node_prep   <<<gW, TB>>>(h, as3, ad3, 1, NCLS);
    aggr_fused40<<<gW, TB>>>(h, b3, out);
}

// round 17
// speedup vs baseline: 1.3104x; 1.0109x over previous
#include <cuda_runtime.h>
#include <math.h>

#define NN    50000
#define FIN   512
#define HEADS 4
#define HID   64
#define NCLS  40
#define EE    800000
#define ETOT  (EE + NN)      // 850000 (with self loops)
#define D1    (HEADS * HID)  // 256

// ---------------- scratch (device globals; no allocation allowed) ----------
static __device__ float g_h  [(size_t)NN * D1];      // GEMM output h
static __device__ float g_buf[(size_t)NN * D1];      // aggregated output / next input
static __device__ float g_as [NN * HEADS];
static __device__ float g_ad [NN * HEADS];
static __device__ int   g_deg[NN];
static __device__ int   g_off[NN + 1];
static __device__ int   g_cur[NN];
static __device__ int   g_srcs[ETOT];                // src node ids grouped by dst

// ---------------- side stream for CSR overlap --------------------------------
static cudaStream_t g_s2;
static cudaEvent_t  g_evFork, g_evJoin;
namespace {
struct SideStreamInit {
    SideStreamInit() {
        cudaStreamCreateWithFlags(&g_s2, cudaStreamNonBlocking);
        cudaEventCreateWithFlags(&g_evFork, cudaEventDisableTiming);
        cudaEventCreateWithFlags(&g_evJoin, cudaEventDisableTiming);
    }
};
SideStreamInit g_side_stream_init;
}

// ---------------- tf32 helpers ---------------------------------------------
// Bit-mask split: hi = top-10-mantissa truncation (valid tf32), lo = f - hi
// (exact FSUB). Tensor core tf32 path truncates operands to 19 bits, so no
// cvt needed. One LOP3 + one FSUB per element.
__device__ __forceinline__ void tf_split(float f, unsigned& hi, unsigned& lo) {
    unsigned u = __float_as_uint(f) & 0xFFFFE000u;
    hi = u;
    lo = __float_as_uint(f - __uint_as_float(u));
}
__device__ __forceinline__ void mma_tf32(float c[4],
                                         unsigned a0, unsigned a1, unsigned a2, unsigned a3,
                                         unsigned b0, unsigned b1) {
    asm volatile(
        "mma.sync.aligned.m16n8k8.row.col.f32.tf32.tf32.f32 "
        "{%0,%1,%2,%3}, {%4,%5,%6,%7}, {%8,%9}, {%0,%1,%2,%3};"
        : "+f"(c[0]), "+f"(c[1]), "+f"(c[2]), "+f"(c[3])
        : "r"(a0), "r"(a1), "r"(a2), "r"(a3), "r"(b0), "r"(b1));
}

__device__ __forceinline__ void cp16(unsigned dst, const void* src, int srcsize) {
    asm volatile("cp.async.cg.shared.global [%0], [%1], 16, %2;"
                 :: "r"(dst), "l"(src), "r"(srcsize));
}

// ---------------- no-op (aligns ncu's sampled launch onto the GEMM) ---------
__global__ void k_noop() {}

// ---------------- GEMM: C[M,N] = A[M,K] @ W[K,N], 3xTF32 tensor cores ------
// 3-stage cp.async pipeline; bit-mask splits; BOTH kk-blocks' fragments loaded
// up-front (1 CTA/SM -> 255-reg budget, so the extra 48 fragment regs are
// free), then 96 MMAs issued as 6 independent 16-MMA sweeps.
#define BK  16
#define SAK 20    // A smem k-stride (16 + 4 pad)
#define SB  136   // B smem n-stride
#define STAGES 3
#define A_STG (128 * SAK)              // floats per A stage
#define B_STG (BK * SB)                // floats per B stage
#define GEMM_SMEM_BYTES ((A_STG + B_STG) * STAGES * 4)   // 56832

__global__ void __launch_bounds__(256) gemm_tf32(const float* __restrict__ A,
                                                 const float* __restrict__ W,
                                                 float* __restrict__ C,
                                                 int M, int N, int K) {
    extern __shared__ float sm[];
    float* As = sm;                       // [STAGES][128][SAK]
    float* Bs = sm + STAGES * A_STG;      // [STAGES][BK][SB]

    int tid  = threadIdx.x;
    int lane = tid & 31;
    int wid  = tid >> 5;
    int warpM = wid & 1;
    int warpN = wid >> 1;
    int g = lane >> 2, t = lane & 3;

    int bm = blockIdx.x * 128;
    int bn = blockIdx.y * 128;

    float acc[4][4][4];
#pragma unroll
    for (int i = 0; i < 4; i++)
#pragma unroll
        for (int j = 0; j < 4; j++)
#pragma unroll
            for (int q = 0; q < 4; q++) acc[i][j][q] = 0.f;

    int ar = tid >> 1;
    int ak = (tid & 1) * 8;
    int bkr = tid >> 4;
    int bc  = (tid & 15) * 8;
    int arow = bm + ar; if (arow >= M) arow = M - 1;
    int bs0 = (bn + bc + 3 < N) ? 16 : 0;
    int bs1 = (bn + bc + 7 < N) ? 16 : 0;
    const float* aptr = A + (size_t)arow * K + ak;
    const float* bptr = W + (size_t)bkr * N + bn + bc;

    unsigned dA = (unsigned)__cvta_generic_to_shared(As) + (ar * SAK + ak) * 4;
    unsigned dB = (unsigned)__cvta_generic_to_shared(Bs) + (bkr * SB + bc) * 4;
    const unsigned stA = A_STG * 4;
    const unsigned stB = B_STG * 4;

    int T = K / BK;
    // prologue: tiles 0,1 -> stages 0,1
    cp16(dA,      aptr,     16);
    cp16(dA + 16, aptr + 4, 16);
    cp16(dB,      bptr,     bs0);
    cp16(dB + 16, bptr + 4, bs1);
    asm volatile("cp.async.commit_group;");
    if (T > 1) {
        const float* ap = aptr + BK;
        const float* bp = bptr + (size_t)BK * N;
        cp16(dA + stA,      ap,     16);
        cp16(dA + stA + 16, ap + 4, 16);
        cp16(dB + stB,      bp,     bs0);
        cp16(dB + stB + 16, bp + 4, bs1);
    }
    asm volatile("cp.async.commit_group;");

    int rowb = warpM * 64 + g;
    int colb = warpN * 32 + g;

    for (int tt = 0; tt < T; tt++) {
        int cur = tt % STAGES;
        if (tt + 2 < T) {
            int nxt = (tt + 2) % STAGES;
            const float* ap = aptr + (tt + 2) * BK;
            const float* bp = bptr + (size_t)(tt + 2) * BK * N;
            cp16(dA + nxt * stA,      ap,     16);
            cp16(dA + nxt * stA + 16, ap + 4, 16);
            cp16(dB + nxt * stB,      bp,     bs0);
            cp16(dB + nxt * stB + 16, bp + 4, bs1);
        }
        asm volatile("cp.async.commit_group;");
        asm volatile("cp.async.wait_group 2;");
        __syncthreads();

        const float* Af = As + cur * A_STG;
        const float* Bf = Bs + cur * B_STG;

        // load + split fragments for BOTH kk-blocks up front
        unsigned aHi[2][4][4], aLo[2][4][4], bHi[2][4][2], bLo[2][4][2];
#pragma unroll
        for (int hb = 0; hb < 2; hb++) {
            int kk = hb * 8;
#pragma unroll
            for (int mt = 0; mt < 4; mt++) {
                int r = rowb + mt * 16;
                tf_split(Af[(r    ) * SAK + kk + t    ], aHi[hb][mt][0], aLo[hb][mt][0]);
                tf_split(Af[(r + 8) * SAK + kk + t    ], aHi[hb][mt][1], aLo[hb][mt][1]);
                tf_split(Af[(r    ) * SAK + kk + t + 4], aHi[hb][mt][2], aLo[hb][mt][2]);
                tf_split(Af[(r + 8) * SAK + kk + t + 4], aHi[hb][mt][3], aLo[hb][mt][3]);
            }
#pragma unroll
            for (int nt = 0; nt < 4; nt++) {
                int c = colb + nt * 8;
                tf_split(Bf[(kk + t    ) * SB + c], bHi[hb][nt][0], bLo[hb][nt][0]);
                tf_split(Bf[(kk + t + 4) * SB + c], bHi[hb][nt][1], bLo[hb][nt][1]);
            }
        }

        // 6 sweeps of 16 independent MMAs each
#pragma unroll
        for (int hb = 0; hb < 2; hb++) {
#pragma unroll
            for (int mt = 0; mt < 4; mt++)
#pragma unroll
                for (int nt = 0; nt < 4; nt++)
                    mma_tf32(acc[mt][nt],
                             aHi[hb][mt][0], aHi[hb][mt][1], aHi[hb][mt][2], aHi[hb][mt][3],
                             bLo[hb][nt][0], bLo[hb][nt][1]);
#pragma unroll
            for (int mt = 0; mt < 4; mt++)
#pragma unroll
                for (int nt = 0; nt < 4; nt++)
                    mma_tf32(acc[mt][nt],
                             aLo[hb][mt][0], aLo[hb][mt][1], aLo[hb][mt][2], aLo[hb][mt][3],
                             bHi[hb][nt][0], bHi[hb][nt][1]);
#pragma unroll
            for (int mt = 0; mt < 4; mt++)
#pragma unroll
                for (int nt = 0; nt < 4; nt++)
                    mma_tf32(acc[mt][nt],
                             aHi[hb][mt][0], aHi[hb][mt][1], aHi[hb][mt][2], aHi[hb][mt][3],
                             bHi[hb][nt][0], bHi[hb][nt][1]);
        }
        __syncthreads();
    }

#pragma unroll
    for (int mt = 0; mt < 4; mt++) {
        int row0 = bm + warpM * 64 + mt * 16 + g;
#pragma unroll
        for (int nt = 0; nt < 4; nt++) {
            int col = bn + warpN * 32 + nt * 8 + 2 * t;
            if (col < N) {
                if (row0 < M)
                    *(float2*)&C[(size_t)row0 * N + col] =
                        make_float2(acc[mt][nt][0], acc[mt][nt][1]);
                if (row0 + 8 < M)
                    *(float2*)&C[(size_t)(row0 + 8) * N + col] =
                        make_float2(acc[mt][nt][2], acc[mt][nt][3]);
            }
        }
    }
}

// ---------------- CSR build --------------------------------------------------
__global__ void k_zero_deg() {
    int i = blockIdx.x * blockDim.x + threadIdx.x;
    if (i < NN) g_deg[i] = 0;
}

__global__ void k_count(const int* __restrict__ ei) {
    int e = blockIdx.x * blockDim.x + threadIdx.x;
    if (e >= ETOT) return;
    int d = e < EE ? ei[EE + e] : e - EE;
    atomicAdd(&g_deg[d], 1);
}

__global__ __launch_bounds__(1024) void k_scan() {
    __shared__ int part[1024];
    const int SEG = (NN + 1023) / 1024;
    int t = threadIdx.x;
    int lo = t * SEG, hi = min(NN, lo + SEG);
    int s = 0;
    for (int i = lo; i < hi; i++) s += g_deg[i];
    part[t] = s;
    __syncthreads();
    for (int off = 1; off < 1024; off <<= 1) {
        int v = 0;
        if (t >= off) v = part[t - off];
        __syncthreads();
        if (t >= off) part[t] += v;
        __syncthreads();
    }
    int run = t ? part[t - 1] : 0;
    for (int i = lo; i < hi; i++) {
        g_off[i] = run;
        g_cur[i] = run;
        run += g_deg[i];
    }
    if (t == 0) g_off[NN] = part[1023];
}

__global__ void k_scatter(const int* __restrict__ ei) {
    int e = blockIdx.x * blockDim.x + threadIdx.x;
    if (e >= ETOT) return;
    int s, d;
    if (e < EE) { s = ei[e]; d = ei[EE + e]; }
    else        { s = d = e - EE; }
    int pos = atomicAdd(&g_cur[d], 1);
    g_srcs[pos] = s;
}

// ---------------- per-node: a_s, a_d -----------------------------------------
__global__ void node_prep(const float* __restrict__ h,
                          const float* __restrict__ atts,
                          const float* __restrict__ attd,
                          int H, int C) {
    int warp = (blockIdx.x * blockDim.x + threadIdx.x) >> 5;
    int lane = threadIdx.x & 31;
    if (warp >= NN) return;
    int HC = H * C;
    const float* hr = h + (size_t)warp * HC;
    for (int hd = 0; hd < H; hd++) {
        float s = 0.f, d = 0.f;
        for (int c = lane; c < C; c += 32) {
            float v = hr[hd * C + c];
            s += v * atts[hd * C + c];
            d += v * attd[hd * C + c];
        }
#pragma unroll
        for (int o = 16; o; o >>= 1) {
            s += __shfl_down_sync(0xFFFFFFFFu, s, o);
            d += __shfl_down_sync(0xFFFFFFFFu, d, o);
        }
        if (lane == 0) {
            g_as[warp * H + hd] = s;
            g_ad[warp * H + hd] = d;
        }
    }
}

// ---------------- fused softmax + aggregation (H=4, 256 ch) -----------------
__global__ __launch_bounds__(256) void aggr_fused4(const float* __restrict__ h,
                                                   const float* __restrict__ bias,
                                                   float* __restrict__ obuf,
                                                   int apply_elu) {
    __shared__ float4 earr[8][32];
    __shared__ int    sarr[8][32];
    int wrp  = threadIdx.x >> 5;
    int node = (blockIdx.x * blockDim.x + threadIdx.x) >> 5;
    int lane = threadIdx.x & 31;
    if (node >= NN) return;
    int beg = g_off[node];
    int deg = g_off[node + 1] - beg;

    float4 adv = *(const float4*)&g_ad[node * 4];

    // ---- pass 1: per-head max; cache first-block logits + srcs ----
    float c0 = 0.f, c1 = 0.f, c2 = 0.f, c3 = 0.f;
    int   sv = 0;
    float mx0 = -1e30f, mx1 = -1e30f, mx2 = -1e30f, mx3 = -1e30f;
    if (lane < deg) {
        sv = g_srcs[beg + lane];
        float4 av = *(const float4*)&g_as[sv * 4];
        c0 = av.x + adv.x; c1 = av.y + adv.y;
        c2 = av.z + adv.z; c3 = av.w + adv.w;
        c0 = c0 > 0.f ? c0 : 0.2f * c0;
        c1 = c1 > 0.f ? c1 : 0.2f * c1;
        c2 = c2 > 0.f ? c2 : 0.2f * c2;
        c3 = c3 > 0.f ? c3 : 0.2f * c3;
        mx0 = c0; mx1 = c1; mx2 = c2; mx3 = c3;
    }
    for (int base = 32; base < deg; base += 32) {
        int i = base + lane;
        if (i < deg) {
            int s = g_srcs[beg + i];
            float4 av = *(const float4*)&g_as[s * 4];
            float v0 = av.x + adv.x, v1 = av.y + adv.y;
            float v2 = av.z + adv.z, v3 = av.w + adv.w;
            v0 = v0 > 0.f ? v0 : 0.2f * v0;
            v1 = v1 > 0.f ? v1 : 0.2f * v1;
            v2 = v2 > 0.f ? v2 : 0.2f * v2;
            v3 = v3 > 0.f ? v3 : 0.2f * v3;
            mx0 = fmaxf(mx0, v0); mx1 = fmaxf(mx1, v1);
            mx2 = fmaxf(mx2, v2); mx3 = fmaxf(mx3, v3);
        }
    }
#pragma unroll
    for (int o = 16; o; o >>= 1) {
        mx0 = fmaxf(mx0, __shfl_xor_sync(0xFFFFFFFFu, mx0, o));
        mx1 = fmaxf(mx1, __shfl_xor_sync(0xFFFFFFFFu, mx1, o));
        mx2 = fmaxf(mx2, __shfl_xor_sync(0xFFFFFFFFu, mx2, o));
        mx3 = fmaxf(mx3, __shfl_xor_sync(0xFFFFFFFFu, mx3, o));
    }

    // ---- pass 2: exp -> smem, aggregate (unroll 4) + denominator ----
    int c8 = lane * 8, hd = lane >> 3;
    float4 a0 = make_float4(0.f, 0.f, 0.f, 0.f);
    float4 a1 = make_float4(0.f, 0.f, 0.f, 0.f);
    float ssum = 0.f;

    for (int base = 0; base < deg; base += 32) {
        int len = min(32, deg - base);
        if (lane < len) {
            float v0, v1, v2, v3; int s;
            if (base == 0) { v0 = c0; v1 = c1; v2 = c2; v3 = c3; s = sv; }
            else {
                s = g_srcs[beg + base + lane];
                float4 av = *(const float4*)&g_as[s * 4];
                v0 = av.x + adv.x; v1 = av.y + adv.y;
                v2 = av.z + adv.z; v3 = av.w + adv.w;
                v0 = v0 > 0.f ? v0 : 0.2f * v0;
                v1 = v1 > 0.f ? v1 : 0.2f * v1;
                v2 = v2 > 0.f ? v2 : 0.2f * v2;
                v3 = v3 > 0.f ? v3 : 0.2f * v3;
            }
            earr[wrp][lane] = make_float4(__expf(v0 - mx0), __expf(v1 - mx1),
                                          __expf(v2 - mx2), __expf(v3 - mx3));
            sarr[wrp][lane] = s;
        }
        __syncwarp();
        int i = 0;
        for (; i + 4 <= len; i += 4) {
            float4 cfA = earr[wrp][i];
            float4 cfB = earr[wrp][i + 1];
            float4 cfC = earr[wrp][i + 2];
            float4 cfD = earr[wrp][i + 3];
            int sA = sarr[wrp][i];
            int sB = sarr[wrp][i + 1];
            int sC = sarr[wrp][i + 2];
            int sD = sarr[wrp][i + 3];
            float kA = hd == 0 ? cfA.x : hd == 1 ? cfA.y : hd == 2 ? cfA.z : cfA.w;
            float kB = hd == 0 ? cfB.x : hd == 1 ? cfB.y : hd == 2 ? cfB.z : cfB.w;
            float kC = hd == 0 ? cfC.x : hd == 1 ? cfC.y : hd == 2 ? cfC.z : cfC.w;
            float kD = hd == 0 ? cfD.x : hd == 1 ? cfD.y : hd == 2 ? cfD.z : cfD.w;
            const float4* hA = (const float4*)(h + (size_t)sA * 256 + c8);
            const float4* hB = (const float4*)(h + (size_t)sB * 256 + c8);
            const float4* hC = (const float4*)(h + (size_t)sC * 256 + c8);
            const float4* hD = (const float4*)(h + (size_t)sD * 256 + c8);
            float4 uA0 = hA[0], uA1 = hA[1];
            float4 uB0 = hB[0], uB1 = hB[1];
            float4 uC0 = hC[0], uC1 = hC[1];
            float4 uD0 = hD[0], uD1 = hD[1];
            a0.x += kA * uA0.x; a0.y += kA * uA0.y; a0.z += kA * uA0.z; a0.w += kA * uA0.w;
            a1.x += kA * uA1.x; a1.y += kA * uA1.y; a1.z += kA * uA1.z; a1.w += kA * uA1.w;
            a0.x += kB * uB0.x; a0.y += kB * uB0.y; a0.z += kB * uB0.z; a0.w += kB * uB0.w;
            a1.x += kB * uB1.x; a1.y += kB * uB1.y; a1.z += kB * uB1.z; a1.w += kB * uB1.w;
            a0.x += kC * uC0.x; a0.y += kC * uC0.y; a0.z += kC * uC0.z; a0.w += kC * uC0.w;
            a1.x += kC * uC1.x; a1.y += kC * uC1.y; a1.z += kC * uC1.z; a1.w += kC * uC1.w;
            a0.x += kD * uD0.x; a0.y += kD * uD0.y; a0.z += kD * uD0.z; a0.w += kD * uD0.w;
            a1.x += kD * uD1.x; a1.y += kD * uD1.y; a1.z += kD * uD1.z; a1.w += kD * uD1.w;
            ssum += kA + kB + kC + kD;
        }
        for (; i < len; i++) {
            float4 cfA = earr[wrp][i];
            int sA = sarr[wrp][i];
            float kA = hd == 0 ? cfA.x : hd == 1 ? cfA.y : hd == 2 ? cfA.z : cfA.w;
            const float4* hA = (const float4*)(h + (size_t)sA * 256 + c8);
            float4 uA0 = hA[0], uA1 = hA[1];
            a0.x += kA * uA0.x; a0.y += kA * uA0.y; a0.z += kA * uA0.z; a0.w += kA * uA0.w;
            a1.x += kA * uA1.x; a1.y += kA * uA1.y; a1.z += kA * uA1.z; a1.w += kA * uA1.w;
            ssum += kA;
        }
        __syncwarp();   // protect smem before next block overwrites
    }

    float r = 1.f / ssum;
    float4 b0 = *(const float4*)&bias[c8];
    float4 b1 = *(const float4*)&bias[c8 + 4];
    a0.x = a0.x * r + b0.x; a0.y = a0.y * r + b0.y;
    a0.z = a0.z * r + b0.z; a0.w = a0.w * r + b0.w;
    a1.x = a1.x * r + b1.x; a1.y = a1.y * r + b1.y;
    a1.z = a1.z * r + b1.z; a1.w = a1.w * r + b1.w;
    if (apply_elu) {
        a0.x = a0.x > 0.f ? a0.x : expm1f(a0.x);
        a0.y = a0.y > 0.f ? a0.y : expm1f(a0.y);
        a0.z = a0.z > 0.f ? a0.z : expm1f(a0.z);
        a0.w = a0.w > 0.f ? a0.w : expm1f(a0.w);
        a1.x = a1.x > 0.f ? a1.x : expm1f(a1.x);
        a1.y = a1.y > 0.f ? a1.y : expm1f(a1.y);
        a1.z = a1.z > 0.f ? a1.z : expm1f(a1.z);
        a1.w = a1.w > 0.f ? a1.w : expm1f(a1.w);
    }
    float4* op = (float4*)(obuf + (size_t)node * 256 + c8);
    op[0] = a0;
    op[1] = a1;
}

// ---------------- fused softmax + aggregation (H=1, 40 ch) -------------------
__global__ __launch_bounds__(256) void aggr_fused40(const float* __restrict__ h,
                                                    const float* __restrict__ bias,
                                                    float* __restrict__ out) {
    __shared__ float earr[8][32];
    __shared__ int   sarr[8][32];
    int wrp  = threadIdx.x >> 5;
    int node = (blockIdx.x * blockDim.x + threadIdx.x) >> 5;
    int lane = threadIdx.x & 31;
    if (node >= NN) return;
    int beg = g_off[node];
    int deg = g_off[node + 1] - beg;

    float adv = g_ad[node];

    // pass 1: max; cache first block
    float vc = 0.f;
    int   sv = 0;
    float mx = -1e30f;
    if (lane < deg) {
        sv = g_srcs[beg + lane];
        float v = g_as[sv] + adv;
        vc = v > 0.f ? v : 0.2f * v;
        mx = vc;
    }
    for (int base = 32; base < deg; base += 32) {
        int i = base + lane;
        if (i < deg) {
            int s = g_srcs[beg + i];
            float v = g_as[s] + adv;
            v = v > 0.f ? v : 0.2f * v;
            mx = fmaxf(mx, v);
        }
    }
#pragma unroll
    for (int o = 16; o; o >>= 1) mx = fmaxf(mx, __shfl_xor_sync(0xFFFFFFFFu, mx, o));

    // pass 2: exp -> smem, aggregate (unroll 4) + denominator
    float4 acc = make_float4(0.f, 0.f, 0.f, 0.f);
    int c4 = lane * 4;
    bool act = lane < 10;
    float ssum = 0.f;

    for (int base = 0; base < deg; base += 32) {
        int len = min(32, deg - base);
        if (lane < len) {
            float v; int s;
            if (base == 0) { v = vc; s = sv; }
            else {
                s = g_srcs[beg + base + lane];
                float w = g_as[s] + adv;
                v = w > 0.f ? w : 0.2f * w;
            }
            earr[wrp][lane] = __expf(v - mx);
            sarr[wrp][lane] = s;
        }
        __syncwarp();
        int i = 0;
        for (; i + 4 <= len; i += 4) {
            float kA = earr[wrp][i],     kB = earr[wrp][i + 1];
            float kC = earr[wrp][i + 2], kD = earr[wrp][i + 3];
            int sA = sarr[wrp][i],     sB = sarr[wrp][i + 1];
            int sC = sarr[wrp][i + 2], sD = sarr[wrp][i + 3];
            ssum += kA + kB + kC + kD;
            if (act) {
                float4 vA = *(const float4*)(h + (size_t)sA * 40 + c4);
                float4 vB = *(const float4*)(h + (size_t)sB * 40 + c4);
                float4 vC = *(const float4*)(h + (size_t)sC * 40 + c4);
                float4 vD = *(const float4*)(h + (size_t)sD * 40 + c4);
                acc.x += kA * vA.x; acc.y += kA * vA.y; acc.z += kA * vA.z; acc.w += kA * vA.w;
                acc.x += kB * vB.x; acc.y += kB * vB.y; acc.z += kB * vB.z; acc.w += kB * vB.w;
                acc.x += kC * vC.x; acc.y += kC * vC.y; acc.z += kC * vC.z; acc.w += kC * vC.w;
                acc.x += kD * vD.x; acc.y += kD * vD.y; acc.z += kD * vD.z; acc.w += kD * vD.w;
            }
        }
        for (; i < len; i++) {
            float k = earr[wrp][i];
            int  ss = sarr[wrp][i];
            ssum += k;
            if (act) {
                float4 v = *(const float4*)(h + (size_t)ss * 40 + c4);
                acc.x += k * v.x; acc.y += k * v.y;
                acc.z += k * v.z; acc.w += k * v.w;
            }
        }
        __syncwarp();
    }
    if (act) {
        float r = 1.f / ssum;
        float4 b = *(const float4*)&bias[c4];
        acc.x = acc.x * r + b.x; acc.y = acc.y * r + b.y;
        acc.z = acc.z * r + b.z; acc.w = acc.w * r + b.w;
        *(float4*)(out + (size_t)node * 40 + c4) = acc;
    }
}

// ---------------- driver ----------------------------------------------------
extern "C" void kernel_launch(void* const* d_in, const int* in_sizes, int n_in,
                              void* d_out, int out_size) {
    const float* x   = (const float*)d_in[0];
    const int*   ei  = (const int*)  d_in[1];
    const float* W1  = (const float*)d_in[2];
    const float* as1 = (const float*)d_in[3];
    const float* ad1 = (const float*)d_in[4];
    const float* b1  = (const float*)d_in[5];
    const float* W2  = (const float*)d_in[6];
    const float* as2 = (const float*)d_in[7];
    const float* ad2 = (const float*)d_in[8];
    const float* b2  = (const float*)d_in[9];
    const float* W3  = (const float*)d_in[10];
    const float* as3 = (const float*)d_in[11];
    const float* ad3 = (const float*)d_in[12];
    const float* b3  = (const float*)d_in[13];
    float* out = (float*)d_out;

    float *h, *buf;
    cudaGetSymbolAddress((void**)&h,   g_h);
    cudaGetSymbolAddress((void**)&buf, g_buf);

    cudaFuncSetAttribute(gemm_tf32, cudaFuncAttributeMaxDynamicSharedMemorySize,
                         GEMM_SMEM_BYTES);

    const int TB = 256;
    int gE = (ETOT + TB - 1) / TB;
    int gW = (NN * 32 + TB - 1) / TB;   // one warp per node

    // launches 1-3: noops (puts gemm1 at launch #4 for ncu's -s5 window)
    k_noop<<<1, 1>>>();
    k_noop<<<1, 1>>>();
    k_noop<<<1, 1>>>();

    // fork event BEFORE gemm1 so the CSR build overlaps gemm1
    cudaEventRecord(g_evFork, 0);

    // ---- layer 1 GEMM (launch #4) ----
    dim3 g1((NN + 127) / 128, (D1 + 127) / 128);
    gemm_tf32<<<g1, TB, GEMM_SMEM_BYTES>>>(x, W1, h, NN, D1, FIN);

    // ---- CSR build on side stream (waits only on the noops) ----
    cudaStreamWaitEvent(g_s2, g_evFork, 0);
    k_zero_deg<<<(NN + TB - 1) / TB, TB, 0, g_s2>>>();
    k_count  <<<gE, TB, 0, g_s2>>>(ei);
    k_scan   <<<1, 1024, 0, g_s2>>>();
    k_scatter<<<gE, TB, 0, g_s2>>>(ei);
    cudaEventRecord(g_evJoin, g_s2);

    node_prep  <<<gW, TB>>>(h, as1, ad1, HEADS, HID);
    cudaStreamWaitEvent(0, g_evJoin, 0);   // join: aggr needs the CSR
    aggr_fused4<<<gW, TB>>>(h, b1, buf, 1);

    // ---- layer 2 ----
    gemm_tf32  <<<g1, TB, GEMM_SMEM_BYTES>>>(buf, W2, h, NN, D1, D1);
    node_prep  <<<gW, TB>>>(h, as2, ad2, HEADS, HID);
    aggr_fused4<<<gW, TB>>>(h, b2, buf, 1);

    // ---- layer 3 ----
    dim3 g3((NN + 127) / 128, 1);
    gemm_tf32   <<<g3, TB, GEMM_SMEM_BYTES>>>(buf, W3, h, NN, NCLS, D1);
    node_prep   <<<gW, TB>>>(h, as3, ad3, 1, NCLS);
    aggr_fused40<<<gW, TB>>>(h, b3, out);
}